// round 12
// baseline (speedup 1.0000x reference)
#include <cuda_runtime.h>
#include <cuda_bf16.h>
#include <cstdint>

typedef unsigned int u32;
typedef unsigned short u16;

// ---------------------------------------------------------------------------
// Device-global scratch (no allocations allowed). All bf16 stored as ushort.
// ---------------------------------------------------------------------------
__device__ __align__(16) u16 g_XTh[8u*256*2048], g_XTl[8u*256*2048];  // X^T per (b,q): [f=256][t=2048]
__device__ __align__(16) u16 g_Xnh[2u*2048*1024], g_Xnl[2u*2048*1024];// hidden split: [b][t][e]
__device__ __align__(16) u16 g_CTh[16u*65536],   g_CTl[16u*65536];    // C^T per (a,q): [g=256][f=256]
__device__ __align__(16) u16 g_qh [4u*262144],   g_ql [4u*262144];    // queries split: [a][e=256][k=1024]
__device__ __align__(16) float g_Gp[8u*8*65536];                      // gram fp32 partials (z8)
__device__ __align__(16) u16 g_Gh[8u*65536], g_Gl[8u*65536];          // G per (b,q): [256][256]
__device__ __align__(16) u16 g_TTh[8u*262144], g_TTl[8u*262144];      // T^T split: [ba][g=256][k=1024]
__device__ __align__(16) float g_Mp[4u*8*65536];                      // fold fp32 partials (z4)
__device__ __align__(16) u16 g_Mth[8u*65536], g_Mtl[8u*65536];        // M^T per (b,a): [g=256][e=256]

// ---------------------------------------------------------------------------
__device__ __forceinline__ void mma_bf16(float* c, const u32* a, const u32* b) {
    asm("mma.sync.aligned.m16n8k16.row.col.f32.bf16.bf16.f32 "
        "{%0,%1,%2,%3}, {%4,%5,%6,%7}, {%8,%9}, {%0,%1,%2,%3};"
        : "+f"(c[0]), "+f"(c[1]), "+f"(c[2]), "+f"(c[3])
        : "r"(a[0]), "r"(a[1]), "r"(a[2]), "r"(a[3]), "r"(b[0]), "r"(b[1]));
}
__device__ __forceinline__ void ldsm_x4(u32* r, u32 saddr) {
    asm volatile("ldmatrix.sync.aligned.m8n8.x4.shared.b16 {%0,%1,%2,%3}, [%4];"
                 : "=r"(r[0]), "=r"(r[1]), "=r"(r[2]), "=r"(r[3]) : "r"(saddr));
}
__device__ __forceinline__ void cpa16(u32 dst, const void* src) {
    asm volatile("cp.async.cg.shared.global [%0], [%1], 16;" :: "r"(dst), "l"(src));
}
__device__ __forceinline__ void cpa_commit() {
    asm volatile("cp.async.commit_group;" ::: "memory");
}

__device__ __forceinline__ void split2(float v, u16& h, u16& l) {
    __nv_bfloat16 bh = __float2bfloat16(v);
    __nv_bfloat16 bl = __float2bfloat16(v - __bfloat162float(bh));
    h = *reinterpret_cast<u16*>(&bh);
    l = *reinterpret_cast<u16*>(&bl);
}

// SMEM tiles (row stride 40 u16 = 80B): A 128x32, B 64x32, each hi+lo.
constexpr int SK = 40;
constexpr int TSA = 128 * SK;                   // u16, A tile
constexpr int TSB = 64 * SK;                    // u16, B tile
constexpr int BUF = 2 * TSA + 2 * TSB;          // u16 per buffer = 15360
constexpr int SMEM_GEMM = 2 * BUF * 2;          // bytes = 61440

// ---------------------------------------------------------------------------
// cp.async fill of one chunk (A 128x32 h/l, B 64x32 h/l). 128 threads.
// ---------------------------------------------------------------------------
__device__ __forceinline__ void issue_chunk(u16* buf,
    const u16* __restrict__ Ah, const u16* __restrict__ Al, size_t lda,
    const u16* __restrict__ Bh, const u16* __restrict__ Bl, size_t ldb, int k0)
{
    u16* sAh = buf;            u16* sAl = buf + TSA;
    u16* sBh = buf + 2 * TSA;  u16* sBl = buf + 2 * TSA + TSB;
    #pragma unroll
    for (int u = threadIdx.x; u < 512; u += 128) {
        int row = u >> 2, c = u & 3;
        int so = row * SK + c * 8;
        size_t go = (size_t)row * lda + k0 + c * 8;
        cpa16((u32)__cvta_generic_to_shared(sAh + so), Ah + go);
        cpa16((u32)__cvta_generic_to_shared(sAl + so), Al + go);
    }
    #pragma unroll
    for (int u = threadIdx.x; u < 256; u += 128) {
        int row = u >> 2, c = u & 3;
        int so = row * SK + c * 8;
        size_t go = (size_t)row * ldb + k0 + c * 8;
        cpa16((u32)__cvta_generic_to_shared(sBh + so), Bh + go);
        cpa16((u32)__cvta_generic_to_shared(sBl + so), Bl + go);
    }
    cpa_commit();
}

// ---------------------------------------------------------------------------
// Core: C[128,64](fp32) = sum_k (Ah+Al)[128,k]*(Bh+Bl)[64,k]^T (hh+hl+lh)
// 128 threads = 4 warps (2m x 2n), warp tile 64x32.
// TWO accumulator sets: accA <- hh, accB <- hl+lh. No same-acc MMA chains —
// the dependency graph itself is chain-free, whatever order ptxas picks.
// ---------------------------------------------------------------------------
template <bool SPLIT_OUT>
__device__ void gemm_ss(const u16* __restrict__ Ah, const u16* __restrict__ Al, size_t lda,
                        const u16* __restrict__ Bh, const u16* __restrict__ Bl, size_t ldb,
                        int kbeg, int kend,
                        float* __restrict__ C, u16* __restrict__ Ch, u16* __restrict__ Cl,
                        size_t ldc)
{
    extern __shared__ __align__(16) u16 dsmem[];
    u16* bufs[2] = { dsmem, dsmem + BUF };

    const int tid = threadIdx.x, w = tid >> 5, lane = tid & 31;
    const int wm = (w >> 1) * 64, wn = (w & 1) * 32;
    const int ty = lane >> 2, tk = lane & 3;

    float accA[4][4][4] = {};   // hh      [mt][nt(n8)][frag]
    float accB[4][4][4] = {};   // hl + lh

    const int nchunk = (kend - kbeg) >> 5;
    issue_chunk(bufs[0], Ah, Al, lda, Bh, Bl, ldb, kbeg);

    for (int i = 0; i < nchunk; i++) {
        const bool has_next = (i + 1) < nchunk;
        if (has_next)
            issue_chunk(bufs[(i + 1) & 1], Ah, Al, lda, Bh, Bl, ldb, kbeg + (i + 1) * 32);
        if (has_next) asm volatile("cp.async.wait_group 1;" ::: "memory");
        else          asm volatile("cp.async.wait_group 0;" ::: "memory");
        __syncthreads();

        u16* buf = bufs[i & 1];
        const u32 bAh = (u32)__cvta_generic_to_shared(buf);
        const u32 bAl = bAh + TSA * 2;
        const u32 bBh = bAh + 2 * TSA * 2;
        const u32 bBl = bAh + (2 * TSA + TSB) * 2;

        #pragma unroll
        for (int ks = 0; ks < 2; ks++) {
            const int kb = ks * 16;
            // B fragments (hi+lo), 2 np groups x two n8 tiles each
            u32 bh[2][4], bl[2][4];
            #pragma unroll
            for (int np = 0; np < 2; np++) {
                u32 off = ((wn + np * 16 + (lane & 7) + ((lane >> 4) & 1) * 8) * SK
                           + kb + ((lane >> 3) & 1) * 8) * 2;
                ldsm_x4(bh[np], bBh + off);
                ldsm_x4(bl[np], bBl + off);
            }
            #pragma unroll
            for (int mt = 0; mt < 4; mt++) {
                u32 off = ((wm + mt * 16 + (lane & 15)) * SK + kb + (lane >> 4) * 8) * 2;
                u32 ah[4], al[4];
                ldsm_x4(ah, bAh + off);
                ldsm_x4(al, bAl + off);
                // hh -> accA, hl -> accB (all distinct accs back-to-back)
                #pragma unroll
                for (int np = 0; np < 2; np++) {
                    mma_bf16(accA[mt][2*np],   ah, bh[np]);
                    mma_bf16(accA[mt][2*np+1], ah, bh[np] + 2);
                    mma_bf16(accB[mt][2*np],   ah, bl[np]);
                    mma_bf16(accB[mt][2*np+1], ah, bl[np] + 2);
                }
                // lh -> accB (>=6 MMAs after the hl write to the same acc)
                #pragma unroll
                for (int np = 0; np < 2; np++) {
                    mma_bf16(accB[mt][2*np],   al, bh[np]);
                    mma_bf16(accB[mt][2*np+1], al, bh[np] + 2);
                }
            }
        }
        __syncthreads();
    }

    // epilogue: sum the two sets in fp32, store
    #pragma unroll
    for (int mt = 0; mt < 4; mt++) {
        int m = wm + mt * 16 + ty;
        #pragma unroll
        for (int nt = 0; nt < 4; nt++) {
            int n = wn + nt * 8 + tk * 2;
            float c0 = accA[mt][nt][0] + accB[mt][nt][0];
            float c1 = accA[mt][nt][1] + accB[mt][nt][1];
            float c2 = accA[mt][nt][2] + accB[mt][nt][2];
            float c3 = accA[mt][nt][3] + accB[mt][nt][3];
            if (SPLIT_OUT) {
                u16 h0, l0, h1, l1, h2, l2, h3, l3;
                split2(c0, h0, l0); split2(c1, h1, l1);
                split2(c2, h2, l2); split2(c3, h3, l3);
                *reinterpret_cast<ushort2*>(&Ch[(size_t)m * ldc + n]) = make_ushort2(h0, h1);
                *reinterpret_cast<ushort2*>(&Cl[(size_t)m * ldc + n]) = make_ushort2(l0, l1);
                *reinterpret_cast<ushort2*>(&Ch[(size_t)(m + 8) * ldc + n]) = make_ushort2(h2, h3);
                *reinterpret_cast<ushort2*>(&Cl[(size_t)(m + 8) * ldc + n]) = make_ushort2(l2, l3);
            } else {
                *reinterpret_cast<float2*>(&C[(size_t)m * ldc + n]) = make_float2(c0, c1);
                *reinterpret_cast<float2*>(&C[(size_t)(m + 8) * ldc + n]) = make_float2(c2, c3);
            }
        }
    }
}

// ---------------------------------------------------------------------------
// Prep kernels (fp32 -> bf16 hi/lo, with transposes)
// ---------------------------------------------------------------------------
__global__ void __launch_bounds__(256) p_hid(const float* __restrict__ hidden)
{
    __shared__ float tile[64][65];
    const int tid = threadIdx.x;
    const int e0 = blockIdx.x * 64, t0 = blockIdx.y * 64, b = blockIdx.z;
    const size_t base = (size_t)b * 2048 * 1024;
    for (int i = tid; i < 4096; i += 256) {
        int r = i >> 6, c = i & 63;
        float v = hidden[base + (size_t)(t0 + r) * 1024 + e0 + c];
        tile[r][c] = v;
        u16 h, l; split2(v, h, l);
        size_t o = base + (size_t)(t0 + r) * 1024 + e0 + c;
        g_Xnh[o] = h; g_Xnl[o] = l;
    }
    __syncthreads();
    const int pair = b * 4 + (e0 >> 8), f0 = e0 & 255;
    for (int i = tid; i < 4096; i += 256) {
        int fl = i >> 6, tl = i & 63;
        u16 h, l; split2(tile[tl][fl], h, l);
        size_t o = (size_t)pair * 524288 + (size_t)(f0 + fl) * 2048 + t0 + tl;
        g_XTh[o] = h; g_XTl[o] = l;
    }
}

__global__ void __launch_bounds__(256) p_comb(const float* __restrict__ comb)
{
    __shared__ float tile[64][65];
    const int tid = threadIdx.x;
    const int g0 = blockIdx.x * 64, k0 = blockIdx.y * 64, a = blockIdx.z;
    for (int i = tid; i < 4096; i += 256) {
        int r = i >> 6, c = i & 63;
        tile[r][c] = comb[(size_t)a * 262144 + (size_t)(k0 + r) * 256 + g0 + c];
    }
    __syncthreads();
    const int q = k0 >> 8, f0 = k0 & 255;
    for (int i = tid; i < 4096; i += 256) {
        int gl = i >> 6, fl = i & 63;
        u16 h, l; split2(tile[fl][gl], h, l);
        size_t o = (size_t)(a * 4 + q) * 65536 + (size_t)(g0 + gl) * 256 + f0 + fl;
        g_CTh[o] = h; g_CTl[o] = l;
    }
}

__global__ void __launch_bounds__(256) p_q(const float* __restrict__ queries)
{
    const int i = blockIdx.x * 256 + threadIdx.x;      // 262144 float4
    float4 v = reinterpret_cast<const float4*>(queries)[i];
    ushort4 h, l;
    split2(v.x, h.x, l.x); split2(v.y, h.y, l.y);
    split2(v.z, h.z, l.z); split2(v.w, h.w, l.w);
    reinterpret_cast<ushort4*>(g_qh)[i] = h;
    reinterpret_cast<ushort4*>(g_ql)[i] = l;
}

// ---------------------------------------------------------------------------
// GEMM stages (128 threads; CTA tile 128x64)
// ---------------------------------------------------------------------------
// Gram: D[f,f'] = sum_t XT[f,t] XT[f',t]  — grid (8, 8 pairs, 8 z)
__global__ void __launch_bounds__(128) k_gram()
{
    const int pair = blockIdx.y, z = blockIdx.z;
    const int m0 = (blockIdx.x >> 2) * 128, n0 = (blockIdx.x & 3) * 64;
    const u16* base_h = g_XTh + (size_t)pair * 524288;
    const u16* base_l = g_XTl + (size_t)pair * 524288;
    float* C = g_Gp + (size_t)(z * 8 + pair) * 65536 + (size_t)m0 * 256 + n0;
    gemm_ss<false>(base_h + (size_t)m0 * 2048, base_l + (size_t)m0 * 2048, 2048,
                   base_h + (size_t)n0 * 2048, base_l + (size_t)n0 * 2048, 2048,
                   z * 256, z * 256 + 256, C, nullptr, nullptr, 256);
}

__global__ void __launch_bounds__(256) k_gred()
{
    const int i = blockIdx.x * 256 + threadIdx.x;      // 131072 float4
    const float4* P = reinterpret_cast<const float4*>(g_Gp);
    float4 s = P[i];
    #pragma unroll
    for (int z = 1; z < 8; z++) {
        float4 t = P[i + (size_t)z * 131072];
        s.x += t.x; s.y += t.y; s.z += t.z; s.w += t.w;
    }
    ushort4 h, l;
    split2(s.x, h.x, l.x); split2(s.y, h.y, l.y);
    split2(s.z, h.z, l.z); split2(s.w, h.w, l.w);
    reinterpret_cast<ushort4*>(g_Gh)[i] = h;
    reinterpret_cast<ushort4*>(g_Gl)[i] = l;
}

// B1: TT[ba][g, q*256+f] = sum_{f'} CT[a,q][g,f'] G[b,q][f,f'] — grid (8, 32)
__global__ void __launch_bounds__(128) k_b1()
{
    const int combo = blockIdx.y, q = combo & 3, ba = combo >> 2;
    const int a = ba & 3, b = ba >> 2;
    const int m0 = (blockIdx.x >> 2) * 128, n0 = (blockIdx.x & 3) * 64;
    const u16* Ah = g_CTh + (size_t)(a * 4 + q) * 65536 + (size_t)m0 * 256;
    const u16* Al = g_CTl + (size_t)(a * 4 + q) * 65536 + (size_t)m0 * 256;
    const u16* Bh = g_Gh + (size_t)(b * 4 + q) * 65536 + (size_t)n0 * 256;
    const u16* Bl = g_Gl + (size_t)(b * 4 + q) * 65536 + (size_t)n0 * 256;
    size_t off = (size_t)ba * 262144 + (size_t)m0 * 1024 + q * 256 + n0;
    gemm_ss<true>(Ah, Al, 256, Bh, Bl, 256, 0, 256,
                  nullptr, g_TTh + off, g_TTl + off, 1024);
}

// B2: Mt[g,e] = sum_k TT[ba][g,k] q[a][e,k] — grid (8, 8 ba, 4 z)
__global__ void __launch_bounds__(128) k_b2()
{
    const int ba = blockIdx.y, z = blockIdx.z, a = ba & 3;
    const int m0 = (blockIdx.x >> 2) * 128, n0 = (blockIdx.x & 3) * 64;
    const u16* Ah = g_TTh + (size_t)ba * 262144 + (size_t)m0 * 1024;
    const u16* Al = g_TTl + (size_t)ba * 262144 + (size_t)m0 * 1024;
    const u16* Bh = g_qh + (size_t)a * 262144 + (size_t)n0 * 1024;
    const u16* Bl = g_ql + (size_t)a * 262144 + (size_t)n0 * 1024;
    float* C = g_Mp + (size_t)(z * 8 + ba) * 65536 + (size_t)m0 * 256 + n0;
    gemm_ss<false>(Ah, Al, 1024, Bh, Bl, 1024, z * 256, z * 256 + 256,
                   C, nullptr, nullptr, 256);
}

__global__ void __launch_bounds__(256) k_mred()
{
    const int i = blockIdx.x * 256 + threadIdx.x;      // 131072 float4
    const float4* P = reinterpret_cast<const float4*>(g_Mp);
    float4 s = P[i];
    #pragma unroll
    for (int z = 1; z < 4; z++) {
        float4 t = P[i + (size_t)z * 131072];
        s.x += t.x; s.y += t.y; s.z += t.z; s.w += t.w;
    }
    ushort4 h, l;
    split2(s.x, h.x, l.x); split2(s.y, h.y, l.y);
    split2(s.z, h.z, l.z); split2(s.w, h.w, l.w);
    reinterpret_cast<ushort4*>(g_Mth)[i] = h;
    reinterpret_cast<ushort4*>(g_Mtl)[i] = l;
}

// C: out[b,t,a*256+g] = sum_e Xn[b,t,a*256+e] Mt[ba][g,e] — grid (64, 8 ba)
__global__ void __launch_bounds__(128) k_c(float* __restrict__ out)
{
    const int ba = blockIdx.y, b = ba >> 2, a = ba & 3;
    const int m0 = (blockIdx.x >> 2) * 128, n0 = (blockIdx.x & 3) * 64;
    const u16* Ah = g_Xnh + (size_t)b * 2097152 + (size_t)m0 * 1024 + a * 256;
    const u16* Al = g_Xnl + (size_t)b * 2097152 + (size_t)m0 * 1024 + a * 256;
    const u16* Bh = g_Mth + (size_t)ba * 65536 + (size_t)n0 * 256;
    const u16* Bl = g_Mtl + (size_t)ba * 65536 + (size_t)n0 * 256;
    float* C = out + (size_t)b * 2097152 + (size_t)m0 * 1024 + a * 256 + n0;
    gemm_ss<false>(Ah, Al, 1024, Bh, Bl, 256, 0, 256, C, nullptr, nullptr, 1024);
}

// ---------------------------------------------------------------------------
extern "C" void kernel_launch(void* const* d_in, const int* in_sizes, int n_in,
                              void* d_out, int out_size)
{
    const float* hidden  = (const float*)d_in[0];   // [2, 2048, 1024]
    const float* queries = (const float*)d_in[1];   // [4, 256, 1024]
    const float* comb    = (const float*)d_in[2];   // [4, 1024, 256]
    float* out = (float*)d_out;                     // [2, 2048, 1024]

    cudaFuncSetAttribute(k_gram, cudaFuncAttributeMaxDynamicSharedMemorySize, SMEM_GEMM);
    cudaFuncSetAttribute(k_b1,   cudaFuncAttributeMaxDynamicSharedMemorySize, SMEM_GEMM);
    cudaFuncSetAttribute(k_b2,   cudaFuncAttributeMaxDynamicSharedMemorySize, SMEM_GEMM);
    cudaFuncSetAttribute(k_c,    cudaFuncAttributeMaxDynamicSharedMemorySize, SMEM_GEMM);

    p_hid <<<dim3(16, 32, 2), 256>>>(hidden);
    p_comb<<<dim3(4, 16, 4), 256>>>(comb);
    p_q   <<<1024, 256>>>(queries);
    k_gram<<<dim3(8, 8, 8), 128, SMEM_GEMM>>>();
    k_gred<<<512, 256>>>();
    k_b1  <<<dim3(8, 32), 128, SMEM_GEMM>>>();
    k_b2  <<<dim3(8, 8, 4), 128, SMEM_GEMM>>>();
    k_mred<<<512, 256>>>();
    k_c   <<<dim3(64, 8), 128, SMEM_GEMM>>>(out);
}

// round 13
// speedup vs baseline: 1.0271x; 1.0271x over previous
#include <cuda_runtime.h>
#include <cuda_bf16.h>
#include <cstdint>

typedef unsigned int u32;
typedef unsigned short u16;

// ---------------------------------------------------------------------------
// Device-global scratch (no allocations allowed). All bf16 stored as ushort.
// ---------------------------------------------------------------------------
__device__ __align__(16) u16 g_XTh[8u*256*2048], g_XTl[8u*256*2048];  // X^T per (b,q): [f=256][t=2048]
__device__ __align__(16) u16 g_Xnh[2u*2048*1024], g_Xnl[2u*2048*1024];// hidden split: [b][t][e]
__device__ __align__(16) u16 g_CTh[16u*65536],   g_CTl[16u*65536];    // C^T per (a,q): [g=256][f=256]
__device__ __align__(16) u16 g_qh [4u*262144],   g_ql [4u*262144];    // queries split: [a][e=256][k=1024]
__device__ __align__(16) float g_Gp[8u*8*65536];                      // gram fp32 partials (z8); only upper blocks written
__device__ __align__(16) u16 g_Gh[8u*65536], g_Gl[8u*65536];          // G per (b,q): [256][256] (full, after mirror)
__device__ __align__(16) u16 g_TTh[8u*262144], g_TTl[8u*262144];      // T^T split: [ba][g=256][k=1024]
__device__ __align__(16) float g_Mp[4u*8*65536];                      // fold fp32 partials (z4)
__device__ __align__(16) u16 g_Mth[8u*65536], g_Mtl[8u*65536];        // M^T per (b,a): [g=256][e=256]

// ---------------------------------------------------------------------------
__device__ __forceinline__ void mma_bf16(float* c, const u32* a, const u32* b) {
    asm("mma.sync.aligned.m16n8k16.row.col.f32.bf16.bf16.f32 "
        "{%0,%1,%2,%3}, {%4,%5,%6,%7}, {%8,%9}, {%0,%1,%2,%3};"
        : "+f"(c[0]), "+f"(c[1]), "+f"(c[2]), "+f"(c[3])
        : "r"(a[0]), "r"(a[1]), "r"(a[2]), "r"(a[3]), "r"(b[0]), "r"(b[1]));
}
__device__ __forceinline__ void ldsm_x4(u32* r, u32 saddr) {
    asm volatile("ldmatrix.sync.aligned.m8n8.x4.shared.b16 {%0,%1,%2,%3}, [%4];"
                 : "=r"(r[0]), "=r"(r[1]), "=r"(r[2]), "=r"(r[3]) : "r"(saddr));
}
__device__ __forceinline__ void cpa16(u32 dst, const void* src) {
    asm volatile("cp.async.cg.shared.global [%0], [%1], 16;" :: "r"(dst), "l"(src));
}
__device__ __forceinline__ void cpa_commit() {
    asm volatile("cp.async.commit_group;" ::: "memory");
}

__device__ __forceinline__ void split2(float v, u16& h, u16& l) {
    __nv_bfloat16 bh = __float2bfloat16(v);
    __nv_bfloat16 bl = __float2bfloat16(v - __bfloat162float(bh));
    h = *reinterpret_cast<u16*>(&bh);
    l = *reinterpret_cast<u16*>(&bl);
}

// SMEM tiles (row stride 40 u16 = 80B): A 128x32, B 64x32, each hi+lo.
constexpr int SK = 40;
constexpr int TSA = 128 * SK;                   // u16, A tile
constexpr int TSB = 64 * SK;                    // u16, B tile
constexpr int BUF = 2 * TSA + 2 * TSB;          // u16 per buffer = 15360
constexpr int SMEM_GEMM = 2 * BUF * 2;          // bytes = 61440

// ---------------------------------------------------------------------------
// cp.async fill of one chunk (A 128x32 h/l, B 64x32 h/l). 128 threads.
// ---------------------------------------------------------------------------
__device__ __forceinline__ void issue_chunk(u16* buf,
    const u16* __restrict__ Ah, const u16* __restrict__ Al, size_t lda,
    const u16* __restrict__ Bh, const u16* __restrict__ Bl, size_t ldb, int k0)
{
    u16* sAh = buf;            u16* sAl = buf + TSA;
    u16* sBh = buf + 2 * TSA;  u16* sBl = buf + 2 * TSA + TSB;
    #pragma unroll
    for (int u = threadIdx.x; u < 512; u += 128) {
        int row = u >> 2, c = u & 3;
        int so = row * SK + c * 8;
        size_t go = (size_t)row * lda + k0 + c * 8;
        cpa16((u32)__cvta_generic_to_shared(sAh + so), Ah + go);
        cpa16((u32)__cvta_generic_to_shared(sAl + so), Al + go);
    }
    #pragma unroll
    for (int u = threadIdx.x; u < 256; u += 128) {
        int row = u >> 2, c = u & 3;
        int so = row * SK + c * 8;
        size_t go = (size_t)row * ldb + k0 + c * 8;
        cpa16((u32)__cvta_generic_to_shared(sBh + so), Bh + go);
        cpa16((u32)__cvta_generic_to_shared(sBl + so), Bl + go);
    }
    cpa_commit();
}

// ---------------------------------------------------------------------------
// Core: C[128,64](fp32) = sum_k (Ah+Al)[128,k]*(Bh+Bl)[64,k]^T (hh+hl+lh)
// 128 threads = 4 warps (2m x 2n), warp tile 64x32. Two accumulator sets.
// ---------------------------------------------------------------------------
template <bool SPLIT_OUT>
__device__ void gemm_ss(const u16* __restrict__ Ah, const u16* __restrict__ Al, size_t lda,
                        const u16* __restrict__ Bh, const u16* __restrict__ Bl, size_t ldb,
                        int kbeg, int kend,
                        float* __restrict__ C, u16* __restrict__ Ch, u16* __restrict__ Cl,
                        size_t ldc)
{
    extern __shared__ __align__(16) u16 dsmem[];
    u16* bufs[2] = { dsmem, dsmem + BUF };

    const int tid = threadIdx.x, w = tid >> 5, lane = tid & 31;
    const int wm = (w >> 1) * 64, wn = (w & 1) * 32;
    const int ty = lane >> 2, tk = lane & 3;

    float accA[4][4][4] = {};   // hh      [mt][nt(n8)][frag]
    float accB[4][4][4] = {};   // hl + lh

    const int nchunk = (kend - kbeg) >> 5;
    issue_chunk(bufs[0], Ah, Al, lda, Bh, Bl, ldb, kbeg);

    for (int i = 0; i < nchunk; i++) {
        const bool has_next = (i + 1) < nchunk;
        if (has_next)
            issue_chunk(bufs[(i + 1) & 1], Ah, Al, lda, Bh, Bl, ldb, kbeg + (i + 1) * 32);
        if (has_next) asm volatile("cp.async.wait_group 1;" ::: "memory");
        else          asm volatile("cp.async.wait_group 0;" ::: "memory");
        __syncthreads();

        u16* buf = bufs[i & 1];
        const u32 bAh = (u32)__cvta_generic_to_shared(buf);
        const u32 bAl = bAh + TSA * 2;
        const u32 bBh = bAh + 2 * TSA * 2;
        const u32 bBl = bAh + (2 * TSA + TSB) * 2;

        #pragma unroll
        for (int ks = 0; ks < 2; ks++) {
            const int kb = ks * 16;
            u32 bh[2][4], bl[2][4];
            #pragma unroll
            for (int np = 0; np < 2; np++) {
                u32 off = ((wn + np * 16 + (lane & 7) + ((lane >> 4) & 1) * 8) * SK
                           + kb + ((lane >> 3) & 1) * 8) * 2;
                ldsm_x4(bh[np], bBh + off);
                ldsm_x4(bl[np], bBl + off);
            }
            #pragma unroll
            for (int mt = 0; mt < 4; mt++) {
                u32 off = ((wm + mt * 16 + (lane & 15)) * SK + kb + (lane >> 4) * 8) * 2;
                u32 ah[4], al[4];
                ldsm_x4(ah, bAh + off);
                ldsm_x4(al, bAl + off);
                #pragma unroll
                for (int np = 0; np < 2; np++) {
                    mma_bf16(accA[mt][2*np],   ah, bh[np]);
                    mma_bf16(accA[mt][2*np+1], ah, bh[np] + 2);
                    mma_bf16(accB[mt][2*np],   ah, bl[np]);
                    mma_bf16(accB[mt][2*np+1], ah, bl[np] + 2);
                }
                #pragma unroll
                for (int np = 0; np < 2; np++) {
                    mma_bf16(accB[mt][2*np],   al, bh[np]);
                    mma_bf16(accB[mt][2*np+1], al, bh[np] + 2);
                }
            }
        }
        __syncthreads();
    }

    #pragma unroll
    for (int mt = 0; mt < 4; mt++) {
        int m = wm + mt * 16 + ty;
        #pragma unroll
        for (int nt = 0; nt < 4; nt++) {
            int n = wn + nt * 8 + tk * 2;
            float c0 = accA[mt][nt][0] + accB[mt][nt][0];
            float c1 = accA[mt][nt][1] + accB[mt][nt][1];
            float c2 = accA[mt][nt][2] + accB[mt][nt][2];
            float c3 = accA[mt][nt][3] + accB[mt][nt][3];
            if (SPLIT_OUT) {
                u16 h0, l0, h1, l1, h2, l2, h3, l3;
                split2(c0, h0, l0); split2(c1, h1, l1);
                split2(c2, h2, l2); split2(c3, h3, l3);
                *reinterpret_cast<ushort2*>(&Ch[(size_t)m * ldc + n]) = make_ushort2(h0, h1);
                *reinterpret_cast<ushort2*>(&Cl[(size_t)m * ldc + n]) = make_ushort2(l0, l1);
                *reinterpret_cast<ushort2*>(&Ch[(size_t)(m + 8) * ldc + n]) = make_ushort2(h2, h3);
                *reinterpret_cast<ushort2*>(&Cl[(size_t)(m + 8) * ldc + n]) = make_ushort2(l2, l3);
            } else {
                *reinterpret_cast<float2*>(&C[(size_t)m * ldc + n]) = make_float2(c0, c1);
                *reinterpret_cast<float2*>(&C[(size_t)(m + 8) * ldc + n]) = make_float2(c2, c3);
            }
        }
    }
}

// ---------------------------------------------------------------------------
// Merged prep kernel: all three fp32 -> bf16 hi/lo preps in ONE launch.
// Block ranges: [0,1024) p_hid (16,32,2) | [1024,1280) p_comb (4,16,4) | [1280,2304) p_q
// ---------------------------------------------------------------------------
__global__ void __launch_bounds__(256) p_all(const float* __restrict__ hidden,
                                             const float* __restrict__ comb,
                                             const float* __restrict__ queries)
{
    __shared__ float tile[64][65];
    const int tid = threadIdx.x;
    const int bid = blockIdx.x;

    if (bid < 1024) {
        // p_hid: e-tile = bid%16, t-tile = (bid/16)%32, b = bid/512
        const int e0 = (bid & 15) * 64, t0 = ((bid >> 4) & 31) * 64, b = bid >> 9;
        const size_t base = (size_t)b * 2048 * 1024;
        for (int i = tid; i < 4096; i += 256) {
            int r = i >> 6, c = i & 63;
            float v = hidden[base + (size_t)(t0 + r) * 1024 + e0 + c];
            tile[r][c] = v;
            u16 h, l; split2(v, h, l);
            size_t o = base + (size_t)(t0 + r) * 1024 + e0 + c;
            g_Xnh[o] = h; g_Xnl[o] = l;
        }
        __syncthreads();
        const int pair = b * 4 + (e0 >> 8), f0 = e0 & 255;
        for (int i = tid; i < 4096; i += 256) {
            int fl = i >> 6, tl = i & 63;
            u16 h, l; split2(tile[tl][fl], h, l);
            size_t o = (size_t)pair * 524288 + (size_t)(f0 + fl) * 2048 + t0 + tl;
            g_XTh[o] = h; g_XTl[o] = l;
        }
    } else if (bid < 1280) {
        // p_comb: j in [0,256): g-tile = j%4, k-tile = (j/4)%16, a = j/64
        const int j = bid - 1024;
        const int g0 = (j & 3) * 64, k0 = ((j >> 2) & 15) * 64, a = j >> 6;
        for (int i = tid; i < 4096; i += 256) {
            int r = i >> 6, c = i & 63;
            tile[r][c] = comb[(size_t)a * 262144 + (size_t)(k0 + r) * 256 + g0 + c];
        }
        __syncthreads();
        const int q = k0 >> 8, f0 = k0 & 255;
        for (int i = tid; i < 4096; i += 256) {
            int gl = i >> 6, fl = i & 63;
            u16 h, l; split2(tile[fl][gl], h, l);
            size_t o = (size_t)(a * 4 + q) * 65536 + (size_t)(g0 + gl) * 256 + f0 + fl;
            g_CTh[o] = h; g_CTl[o] = l;
        }
    } else {
        // p_q: 1024 blocks over 262144 float4
        const int i = (bid - 1280) * 256 + tid;
        float4 v = reinterpret_cast<const float4*>(queries)[i];
        ushort4 h, l;
        split2(v.x, h.x, l.x); split2(v.y, h.y, l.y);
        split2(v.z, h.z, l.z); split2(v.w, h.w, l.w);
        reinterpret_cast<ushort4*>(g_qh)[i] = h;
        reinterpret_cast<ushort4*>(g_ql)[i] = l;
    }
}

// ---------------------------------------------------------------------------
// Gram (SYMMETRIC): only upper 3 of 4 128x128 super-blocks computed.
// grid (6, 8 pairs, 8 z); tile map t -> (mi, ni64):
//   t<4: (0, t) ; t=4: (1,2) ; t=5: (1,3)
// ---------------------------------------------------------------------------
__global__ void __launch_bounds__(128) k_gram()
{
    const int pair = blockIdx.y, z = blockIdx.z;
    const int t = blockIdx.x;
    const int mi = (t >= 4) ? 1 : 0;
    const int ni = mi ? (t - 2) : t;
    const int m0 = mi * 128, n0 = ni * 64;
    const u16* base_h = g_XTh + (size_t)pair * 524288;
    const u16* base_l = g_XTl + (size_t)pair * 524288;
    float* C = g_Gp + (size_t)(z * 8 + pair) * 65536 + (size_t)m0 * 256 + n0;
    gemm_ss<false>(base_h + (size_t)m0 * 2048, base_l + (size_t)m0 * 2048, 2048,
                   base_h + (size_t)n0 * 2048, base_l + (size_t)n0 * 2048, 2048,
                   z * 256, z * 256 + 256, C, nullptr, nullptr, 256);
}

// Reduce z-partials; lower-left super-block reconstructed from symmetry
// (each z-partial is itself symmetric: X_z^T X_z).
__global__ void __launch_bounds__(256) k_gred()
{
    const int i = blockIdx.x * 256 + threadIdx.x;      // 131072 float4 (8 pairs x 16384)
    const int pair = i >> 14;
    const int off = i & 16383;
    const int r = off >> 6;
    const int c = (off & 63) * 4;
    float4 s;
    if (r >= 128 && c < 128) {
        // mirror: G[r, c+j] = sum_z Gp[z,pair][(c+j)*256 + r]
        float v0 = 0.f, v1 = 0.f, v2 = 0.f, v3 = 0.f;
        #pragma unroll
        for (int z = 0; z < 8; z++) {
            const float* P = g_Gp + (((size_t)z * 8 + pair) << 16);
            v0 += P[(size_t)(c + 0) * 256 + r];
            v1 += P[(size_t)(c + 1) * 256 + r];
            v2 += P[(size_t)(c + 2) * 256 + r];
            v3 += P[(size_t)(c + 3) * 256 + r];
        }
        s = make_float4(v0, v1, v2, v3);
    } else {
        const float4* P = reinterpret_cast<const float4*>(g_Gp);
        s = P[i];
        #pragma unroll
        for (int z = 1; z < 8; z++) {
            float4 t = P[i + (size_t)z * 131072];
            s.x += t.x; s.y += t.y; s.z += t.z; s.w += t.w;
        }
    }
    ushort4 h, l;
    split2(s.x, h.x, l.x); split2(s.y, h.y, l.y);
    split2(s.z, h.z, l.z); split2(s.w, h.w, l.w);
    reinterpret_cast<ushort4*>(g_Gh)[i] = h;
    reinterpret_cast<ushort4*>(g_Gl)[i] = l;
}

// B1: TT[ba][g, q*256+f] = sum_{f'} CT[a,q][g,f'] G[b,q][f,f'] — grid (8, 32)
__global__ void __launch_bounds__(128) k_b1()
{
    const int combo = blockIdx.y, q = combo & 3, ba = combo >> 2;
    const int a = ba & 3, b = ba >> 2;
    const int m0 = (blockIdx.x >> 2) * 128, n0 = (blockIdx.x & 3) * 64;
    const u16* Ah = g_CTh + (size_t)(a * 4 + q) * 65536 + (size_t)m0 * 256;
    const u16* Al = g_CTl + (size_t)(a * 4 + q) * 65536 + (size_t)m0 * 256;
    const u16* Bh = g_Gh + (size_t)(b * 4 + q) * 65536 + (size_t)n0 * 256;
    const u16* Bl = g_Gl + (size_t)(b * 4 + q) * 65536 + (size_t)n0 * 256;
    size_t off = (size_t)ba * 262144 + (size_t)m0 * 1024 + q * 256 + n0;
    gemm_ss<true>(Ah, Al, 256, Bh, Bl, 256, 0, 256,
                  nullptr, g_TTh + off, g_TTl + off, 1024);
}

// B2: Mt[g,e] = sum_k TT[ba][g,k] q[a][e,k] — grid (8, 8 ba, 4 z)
__global__ void __launch_bounds__(128) k_b2()
{
    const int ba = blockIdx.y, z = blockIdx.z, a = ba & 3;
    const int m0 = (blockIdx.x >> 2) * 128, n0 = (blockIdx.x & 3) * 64;
    const u16* Ah = g_TTh + (size_t)ba * 262144 + (size_t)m0 * 1024;
    const u16* Al = g_TTl + (size_t)ba * 262144 + (size_t)m0 * 1024;
    const u16* Bh = g_qh + (size_t)a * 262144 + (size_t)n0 * 1024;
    const u16* Bl = g_ql + (size_t)a * 262144 + (size_t)n0 * 1024;
    float* C = g_Mp + (size_t)(z * 8 + ba) * 65536 + (size_t)m0 * 256 + n0;
    gemm_ss<false>(Ah, Al, 1024, Bh, Bl, 1024, z * 256, z * 256 + 256,
                   C, nullptr, nullptr, 256);
}

__global__ void __launch_bounds__(256) k_mred()
{
    const int i = blockIdx.x * 256 + threadIdx.x;      // 131072 float4
    const float4* P = reinterpret_cast<const float4*>(g_Mp);
    float4 s = P[i];
    #pragma unroll
    for (int z = 1; z < 4; z++) {
        float4 t = P[i + (size_t)z * 131072];
        s.x += t.x; s.y += t.y; s.z += t.z; s.w += t.w;
    }
    ushort4 h, l;
    split2(s.x, h.x, l.x); split2(s.y, h.y, l.y);
    split2(s.z, h.z, l.z); split2(s.w, h.w, l.w);
    reinterpret_cast<ushort4*>(g_Mth)[i] = h;
    reinterpret_cast<ushort4*>(g_Mtl)[i] = l;
}

// C: out[b,t,a*256+g] = sum_e Xn[b,t,a*256+e] Mt[ba][g,e] — grid (64, 8 ba)
__global__ void __launch_bounds__(128) k_c(float* __restrict__ out)
{
    const int ba = blockIdx.y, b = ba >> 2, a = ba & 3;
    const int m0 = (blockIdx.x >> 2) * 128, n0 = (blockIdx.x & 3) * 64;
    const u16* Ah = g_Xnh + (size_t)b * 2097152 + (size_t)m0 * 1024 + a * 256;
    const u16* Al = g_Xnl + (size_t)b * 2097152 + (size_t)m0 * 1024 + a * 256;
    const u16* Bh = g_Mth + (size_t)ba * 65536 + (size_t)n0 * 256;
    const u16* Bl = g_Mtl + (size_t)ba * 65536 + (size_t)n0 * 256;
    float* C = out + (size_t)b * 2097152 + (size_t)m0 * 1024 + a * 256 + n0;
    gemm_ss<false>(Ah, Al, 1024, Bh, Bl, 256, 0, 256, C, nullptr, nullptr, 1024);
}

// ---------------------------------------------------------------------------
extern "C" void kernel_launch(void* const* d_in, const int* in_sizes, int n_in,
                              void* d_out, int out_size)
{
    const float* hidden  = (const float*)d_in[0];   // [2, 2048, 1024]
    const float* queries = (const float*)d_in[1];   // [4, 256, 1024]
    const float* comb    = (const float*)d_in[2];   // [4, 1024, 256]
    float* out = (float*)d_out;                     // [2, 2048, 1024]

    cudaFuncSetAttribute(k_gram, cudaFuncAttributeMaxDynamicSharedMemorySize, SMEM_GEMM);
    cudaFuncSetAttribute(k_b1,   cudaFuncAttributeMaxDynamicSharedMemorySize, SMEM_GEMM);
    cudaFuncSetAttribute(k_b2,   cudaFuncAttributeMaxDynamicSharedMemorySize, SMEM_GEMM);
    cudaFuncSetAttribute(k_c,    cudaFuncAttributeMaxDynamicSharedMemorySize, SMEM_GEMM);

    p_all <<<2304, 256>>>(hidden, comb, queries);
    k_gram<<<dim3(6, 8, 8), 128, SMEM_GEMM>>>();
    k_gred<<<512, 256>>>();
    k_b1  <<<dim3(8, 32), 128, SMEM_GEMM>>>();
    k_b2  <<<dim3(8, 8, 4), 128, SMEM_GEMM>>>();
    k_mred<<<512, 256>>>();
    k_c   <<<dim3(64, 8), 128, SMEM_GEMM>>>(out);
}

// round 14
// speedup vs baseline: 1.2507x; 1.2176x over previous
#include <cuda_runtime.h>
#include <cuda_fp16.h>
#include <cstdint>

typedef unsigned int u32;
typedef unsigned short u16;

// Scales: queries x1024, combiners x1024 => M scaled by 2^20; descale in k_c.
#define DESCALE (1.0f / 1048576.0f)

// ---------------------------------------------------------------------------
// Device-global scratch (no allocations allowed). All fp16 stored as ushort.
// ---------------------------------------------------------------------------
__device__ __align__(16) u16 g_XTh[8u*256*2048], g_XTl[8u*256*2048];  // X^T per (b,q): [f=256][t=2048]
__device__ __align__(16) u16 g_Xnh[2u*2048*1024], g_Xnl[2u*2048*1024];// hidden split: [b][t][e]
__device__ __align__(16) u16 g_CTh[16u*65536],   g_CTl[16u*65536];    // C^T (x1024) per (a,q): [g=256][f=256]
__device__ __align__(16) u16 g_qh [4u*262144];                        // queries (x1024) hi: [a][e=256][k=1024]
__device__ __align__(16) float g_Gp[8u*8*65536];                      // gram fp32 partials (z8); upper blocks only
__device__ __align__(16) u16 g_Gh[8u*65536];                          // G hi per (b,q): [256][256]
__device__ __align__(16) u16 g_TTh[8u*262144], g_TTl[8u*262144];      // T^T split: [ba][g=256][k=1024]
__device__ __align__(16) float g_Mp[4u*8*65536];                      // fold fp32 partials (z4)
__device__ __align__(16) u16 g_Mth[8u*65536];                         // M^T hi per (b,a): [g=256][e=256]

// ---------------------------------------------------------------------------
__device__ __forceinline__ void mma_f16(float* c, const u32* a, const u32* b) {
    asm("mma.sync.aligned.m16n8k16.row.col.f32.f16.f16.f32 "
        "{%0,%1,%2,%3}, {%4,%5,%6,%7}, {%8,%9}, {%0,%1,%2,%3};"
        : "+f"(c[0]), "+f"(c[1]), "+f"(c[2]), "+f"(c[3])
        : "r"(a[0]), "r"(a[1]), "r"(a[2]), "r"(a[3]), "r"(b[0]), "r"(b[1]));
}
__device__ __forceinline__ void ldsm_x4(u32* r, u32 saddr) {
    asm volatile("ldmatrix.sync.aligned.m8n8.x4.shared.b16 {%0,%1,%2,%3}, [%4];"
                 : "=r"(r[0]), "=r"(r[1]), "=r"(r[2]), "=r"(r[3]) : "r"(saddr));
}
__device__ __forceinline__ void cpa16(u32 dst, const void* src) {
    asm volatile("cp.async.cg.shared.global [%0], [%1], 16;" :: "r"(dst), "l"(src));
}
__device__ __forceinline__ void cpa_commit() {
    asm volatile("cp.async.commit_group;" ::: "memory");
}

// fp16 hi/lo split (round-to-nearest residual)
__device__ __forceinline__ void split2h(float v, u16& h, u16& l) {
    __half hh = __float2half_rn(v);
    __half ll = __float2half_rn(v - __half2float(hh));
    h = *reinterpret_cast<u16*>(&hh);
    l = *reinterpret_cast<u16*>(&ll);
}

// SMEM tiles (row stride 40 u16 = 80B): A 128x32 (h+l), B 64x32 (h only).
constexpr int SK = 40;
constexpr int TSA = 128 * SK;                   // u16, A tile
constexpr int TSB = 64 * SK;                    // u16, B tile
constexpr int BUF = 2 * TSA + TSB;              // u16 per buffer = 12800
constexpr int SMEM_GEMM = 2 * BUF * 2;          // bytes = 51200

// ---------------------------------------------------------------------------
// cp.async fill of one chunk (A 128x32 h/l, B 64x32 h). 128 threads.
// ---------------------------------------------------------------------------
__device__ __forceinline__ void issue_chunk(u16* buf,
    const u16* __restrict__ Ah, const u16* __restrict__ Al, size_t lda,
    const u16* __restrict__ Bh, size_t ldb, int k0)
{
    u16* sAh = buf;            u16* sAl = buf + TSA;
    u16* sBh = buf + 2 * TSA;
    #pragma unroll
    for (int u = threadIdx.x; u < 512; u += 128) {
        int row = u >> 2, c = u & 3;
        int so = row * SK + c * 8;
        size_t go = (size_t)row * lda + k0 + c * 8;
        cpa16((u32)__cvta_generic_to_shared(sAh + so), Ah + go);
        cpa16((u32)__cvta_generic_to_shared(sAl + so), Al + go);
    }
    #pragma unroll
    for (int u = threadIdx.x; u < 256; u += 128) {
        int row = u >> 2, c = u & 3;
        int so = row * SK + c * 8;
        size_t go = (size_t)row * ldb + k0 + c * 8;
        cpa16((u32)__cvta_generic_to_shared(sBh + so), Bh + go);
    }
    cpa_commit();
}

// ---------------------------------------------------------------------------
// Core: C[128,64](fp32) = sum_k (Ah+Al)[128,k] * Bh[64,k]^T   (hh + lh terms)
// 128 threads = 4 warps (2m x 2n), warp tile 64x32. Two accumulator sets.
// ---------------------------------------------------------------------------
template <bool SPLIT_OUT>
__device__ void gemm_ss(const u16* __restrict__ Ah, const u16* __restrict__ Al, size_t lda,
                        const u16* __restrict__ Bh, size_t ldb,
                        int kbeg, int kend,
                        float* __restrict__ C, u16* __restrict__ Ch, u16* __restrict__ Cl,
                        size_t ldc, float scale)
{
    extern __shared__ __align__(16) u16 dsmem[];
    u16* bufs[2] = { dsmem, dsmem + BUF };

    const int tid = threadIdx.x, w = tid >> 5, lane = tid & 31;
    const int wm = (w >> 1) * 64, wn = (w & 1) * 32;
    const int ty = lane >> 2, tk = lane & 3;

    float accA[4][4][4] = {};   // hh  [mt][nt(n8)][frag]
    float accB[4][4][4] = {};   // lh

    const int nchunk = (kend - kbeg) >> 5;
    issue_chunk(bufs[0], Ah, Al, lda, Bh, ldb, kbeg);

    for (int i = 0; i < nchunk; i++) {
        const bool has_next = (i + 1) < nchunk;
        if (has_next)
            issue_chunk(bufs[(i + 1) & 1], Ah, Al, lda, Bh, ldb, kbeg + (i + 1) * 32);
        if (has_next) asm volatile("cp.async.wait_group 1;" ::: "memory");
        else          asm volatile("cp.async.wait_group 0;" ::: "memory");
        __syncthreads();

        u16* buf = bufs[i & 1];
        const u32 bAh = (u32)__cvta_generic_to_shared(buf);
        const u32 bAl = bAh + TSA * 2;
        const u32 bBh = bAh + 2 * TSA * 2;

        #pragma unroll
        for (int ks = 0; ks < 2; ks++) {
            const int kb = ks * 16;
            u32 bh[2][4];
            #pragma unroll
            for (int np = 0; np < 2; np++) {
                u32 off = ((wn + np * 16 + (lane & 7) + ((lane >> 4) & 1) * 8) * SK
                           + kb + ((lane >> 3) & 1) * 8) * 2;
                ldsm_x4(bh[np], bBh + off);
            }
            #pragma unroll
            for (int mt = 0; mt < 4; mt++) {
                u32 off = ((wm + mt * 16 + (lane & 15)) * SK + kb + (lane >> 4) * 8) * 2;
                u32 ah[4], al[4];
                ldsm_x4(ah, bAh + off);
                ldsm_x4(al, bAl + off);
                #pragma unroll
                for (int np = 0; np < 2; np++) {
                    mma_f16(accA[mt][2*np],   ah, bh[np]);
                    mma_f16(accA[mt][2*np+1], ah, bh[np] + 2);
                    mma_f16(accB[mt][2*np],   al, bh[np]);
                    mma_f16(accB[mt][2*np+1], al, bh[np] + 2);
                }
            }
        }
        __syncthreads();
    }

    #pragma unroll
    for (int mt = 0; mt < 4; mt++) {
        int m = wm + mt * 16 + ty;
        #pragma unroll
        for (int nt = 0; nt < 4; nt++) {
            int n = wn + nt * 8 + tk * 2;
            float c0 = (accA[mt][nt][0] + accB[mt][nt][0]) * scale;
            float c1 = (accA[mt][nt][1] + accB[mt][nt][1]) * scale;
            float c2 = (accA[mt][nt][2] + accB[mt][nt][2]) * scale;
            float c3 = (accA[mt][nt][3] + accB[mt][nt][3]) * scale;
            if (SPLIT_OUT) {
                u16 h0, l0, h1, l1, h2, l2, h3, l3;
                split2h(c0, h0, l0); split2h(c1, h1, l1);
                split2h(c2, h2, l2); split2h(c3, h3, l3);
                *reinterpret_cast<ushort2*>(&Ch[(size_t)m * ldc + n]) = make_ushort2(h0, h1);
                *reinterpret_cast<ushort2*>(&Cl[(size_t)m * ldc + n]) = make_ushort2(l0, l1);
                *reinterpret_cast<ushort2*>(&Ch[(size_t)(m + 8) * ldc + n]) = make_ushort2(h2, h3);
                *reinterpret_cast<ushort2*>(&Cl[(size_t)(m + 8) * ldc + n]) = make_ushort2(l2, l3);
            } else {
                *reinterpret_cast<float2*>(&C[(size_t)m * ldc + n]) = make_float2(c0, c1);
                *reinterpret_cast<float2*>(&C[(size_t)(m + 8) * ldc + n]) = make_float2(c2, c3);
            }
        }
    }
}

// ---------------------------------------------------------------------------
// Merged prep kernel (one launch):
// [0,1024) hidden split+transpose | [1024,1280) comb x1024 | [1280,2304) queries x1024 (hi only)
// ---------------------------------------------------------------------------
__global__ void __launch_bounds__(256) p_all(const float* __restrict__ hidden,
                                             const float* __restrict__ comb,
                                             const float* __restrict__ queries)
{
    __shared__ float tile[64][65];
    const int tid = threadIdx.x;
    const int bid = blockIdx.x;

    if (bid < 1024) {
        const int e0 = (bid & 15) * 64, t0 = ((bid >> 4) & 31) * 64, b = bid >> 9;
        const size_t base = (size_t)b * 2048 * 1024;
        for (int i = tid; i < 4096; i += 256) {
            int r = i >> 6, c = i & 63;
            float v = hidden[base + (size_t)(t0 + r) * 1024 + e0 + c];
            tile[r][c] = v;
            u16 h, l; split2h(v, h, l);
            size_t o = base + (size_t)(t0 + r) * 1024 + e0 + c;
            g_Xnh[o] = h; g_Xnl[o] = l;
        }
        __syncthreads();
        const int pair = b * 4 + (e0 >> 8), f0 = e0 & 255;
        for (int i = tid; i < 4096; i += 256) {
            int fl = i >> 6, tl = i & 63;
            u16 h, l; split2h(tile[tl][fl], h, l);
            size_t o = (size_t)pair * 524288 + (size_t)(f0 + fl) * 2048 + t0 + tl;
            g_XTh[o] = h; g_XTl[o] = l;
        }
    } else if (bid < 1280) {
        const int j = bid - 1024;
        const int g0 = (j & 3) * 64, k0 = ((j >> 2) & 15) * 64, a = j >> 6;
        for (int i = tid; i < 4096; i += 256) {
            int r = i >> 6, c = i & 63;
            tile[r][c] = comb[(size_t)a * 262144 + (size_t)(k0 + r) * 256 + g0 + c] * 1024.0f;
        }
        __syncthreads();
        const int q = k0 >> 8, f0 = k0 & 255;
        for (int i = tid; i < 4096; i += 256) {
            int gl = i >> 6, fl = i & 63;
            u16 h, l; split2h(tile[fl][gl], h, l);
            size_t o = (size_t)(a * 4 + q) * 65536 + (size_t)(g0 + gl) * 256 + f0 + fl;
            g_CTh[o] = h; g_CTl[o] = l;
        }
    } else {
        const int i = (bid - 1280) * 256 + tid;            // 262144 float4
        float4 v = reinterpret_cast<const float4*>(queries)[i];
        u16 hx, lx, hy, ly, hz, lz, hw, lw;
        split2h(v.x * 1024.0f, hx, lx); split2h(v.y * 1024.0f, hy, ly);
        split2h(v.z * 1024.0f, hz, lz); split2h(v.w * 1024.0f, hw, lw);
        ushort4 h = make_ushort4(hx, hy, hz, hw);
        reinterpret_cast<ushort4*>(g_qh)[i] = h;
    }
}

// ---------------------------------------------------------------------------
// Gram (SYMMETRIC upper): grid (6, 8 pairs, 8 z); t<4:(0,t), t=4:(1,2), t=5:(1,3)
// ---------------------------------------------------------------------------
__global__ void __launch_bounds__(128) k_gram()
{
    const int pair = blockIdx.y, z = blockIdx.z;
    const int t = blockIdx.x;
    const int mi = (t >= 4) ? 1 : 0;
    const int ni = mi ? (t - 2) : t;
    const int m0 = mi * 128, n0 = ni * 64;
    const u16* base_h = g_XTh + (size_t)pair * 524288;
    const u16* base_l = g_XTl + (size_t)pair * 524288;
    float* C = g_Gp + (size_t)(z * 8 + pair) * 65536 + (size_t)m0 * 256 + n0;
    gemm_ss<false>(base_h + (size_t)m0 * 2048, base_l + (size_t)m0 * 2048, 2048,
                   base_h + (size_t)n0 * 2048, 2048,
                   z * 256, z * 256 + 256, C, nullptr, nullptr, 256, 1.0f);
}

// Reduce z-partials; mirror lower-left; split hi only (B-side consumer).
__global__ void __launch_bounds__(256) k_gred()
{
    const int i = blockIdx.x * 256 + threadIdx.x;      // 131072 float4
    const int pair = i >> 14;
    const int off = i & 16383;
    const int r = off >> 6;
    const int c = (off & 63) * 4;
    float4 s;
    if (r >= 128 && c < 128) {
        float v0 = 0.f, v1 = 0.f, v2 = 0.f, v3 = 0.f;
        #pragma unroll
        for (int z = 0; z < 8; z++) {
            const float* P = g_Gp + (((size_t)z * 8 + pair) << 16);
            v0 += P[(size_t)(c + 0) * 256 + r];
            v1 += P[(size_t)(c + 1) * 256 + r];
            v2 += P[(size_t)(c + 2) * 256 + r];
            v3 += P[(size_t)(c + 3) * 256 + r];
        }
        s = make_float4(v0, v1, v2, v3);
    } else {
        const float4* P = reinterpret_cast<const float4*>(g_Gp);
        s = P[i];
        #pragma unroll
        for (int z = 1; z < 8; z++) {
            float4 t = P[i + (size_t)z * 131072];
            s.x += t.x; s.y += t.y; s.z += t.z; s.w += t.w;
        }
    }
    u16 h0, l0, h1, l1, h2, l2, h3, l3;
    split2h(s.x, h0, l0); split2h(s.y, h1, l1);
    split2h(s.z, h2, l2); split2h(s.w, h3, l3);
    reinterpret_cast<ushort4*>(g_Gh)[i] = make_ushort4(h0, h1, h2, h3);
}

// B1: TT[ba][g, q*256+f] = sum_{f'} CT[a,q][g,f'] G[b,q][f,f'] — grid (8, 32)
__global__ void __launch_bounds__(128) k_b1()
{
    const int combo = blockIdx.y, q = combo & 3, ba = combo >> 2;
    const int a = ba & 3, b = ba >> 2;
    const int m0 = (blockIdx.x >> 2) * 128, n0 = (blockIdx.x & 3) * 64;
    const u16* Ah = g_CTh + (size_t)(a * 4 + q) * 65536 + (size_t)m0 * 256;
    const u16* Al = g_CTl + (size_t)(a * 4 + q) * 65536 + (size_t)m0 * 256;
    const u16* Bh = g_Gh + (size_t)(b * 4 + q) * 65536 + (size_t)n0 * 256;
    size_t off = (size_t)ba * 262144 + (size_t)m0 * 1024 + q * 256 + n0;
    gemm_ss<true>(Ah, Al, 256, Bh, 256, 0, 256,
                  nullptr, g_TTh + off, g_TTl + off, 1024, 1.0f);
}

// B2: M[g,e] = sum_k TT[ba][g,k] q[a][e,k] — grid (8, 8 ba, 4 z)
__global__ void __launch_bounds__(128) k_b2()
{
    const int ba = blockIdx.y, z = blockIdx.z, a = ba & 3;
    const int m0 = (blockIdx.x >> 2) * 128, n0 = (blockIdx.x & 3) * 64;
    const u16* Ah = g_TTh + (size_t)ba * 262144 + (size_t)m0 * 1024;
    const u16* Al = g_TTl + (size_t)ba * 262144 + (size_t)m0 * 1024;
    const u16* Bh = g_qh + (size_t)a * 262144 + (size_t)n0 * 1024;
    float* C = g_Mp + (size_t)(z * 8 + ba) * 65536 + (size_t)m0 * 256 + n0;
    gemm_ss<false>(Ah, Al, 1024, Bh, 1024, z * 256, z * 256 + 256,
                   C, nullptr, nullptr, 256, 1.0f);
}

// Reduce M partials; split hi only (B-side consumer).
__global__ void __launch_bounds__(256) k_mred()
{
    const int i = blockIdx.x * 256 + threadIdx.x;      // 131072 float4
    const float4* P = reinterpret_cast<const float4*>(g_Mp);
    float4 s = P[i];
    #pragma unroll
    for (int z = 1; z < 4; z++) {
        float4 t = P[i + (size_t)z * 131072];
        s.x += t.x; s.y += t.y; s.z += t.z; s.w += t.w;
    }
    u16 h0, l0, h1, l1, h2, l2, h3, l3;
    split2h(s.x, h0, l0); split2h(s.y, h1, l1);
    split2h(s.z, h2, l2); split2h(s.w, h3, l3);
    reinterpret_cast<ushort4*>(g_Mth)[i] = make_ushort4(h0, h1, h2, h3);
}

// C: out[b,t,a*256+g] = 2^-20 * sum_e Xn[b,t,a*256+e] Mt[ba][g,e] — grid (64, 8 ba)
__global__ void __launch_bounds__(128) k_c(float* __restrict__ out)
{
    const int ba = blockIdx.y, b = ba >> 2, a = ba & 3;
    const int m0 = (blockIdx.x >> 2) * 128, n0 = (blockIdx.x & 3) * 64;
    const u16* Ah = g_Xnh + (size_t)b * 2097152 + (size_t)m0 * 1024 + a * 256;
    const u16* Al = g_Xnl + (size_t)b * 2097152 + (size_t)m0 * 1024 + a * 256;
    const u16* Bh = g_Mth + (size_t)ba * 65536 + (size_t)n0 * 256;
    float* C = out + (size_t)b * 2097152 + (size_t)m0 * 1024 + a * 256 + n0;
    gemm_ss<false>(Ah, Al, 1024, Bh, 256, 0, 256, C, nullptr, nullptr, 1024, DESCALE);
}

// ---------------------------------------------------------------------------
extern "C" void kernel_launch(void* const* d_in, const int* in_sizes, int n_in,
                              void* d_out, int out_size)
{
    const float* hidden  = (const float*)d_in[0];   // [2, 2048, 1024]
    const float* queries = (const float*)d_in[1];   // [4, 256, 1024]
    const float* comb    = (const float*)d_in[2];   // [4, 1024, 256]
    float* out = (float*)d_out;                     // [2, 2048, 1024]

    cudaFuncSetAttribute(k_gram, cudaFuncAttributeMaxDynamicSharedMemorySize, SMEM_GEMM);
    cudaFuncSetAttribute(k_b1,   cudaFuncAttributeMaxDynamicSharedMemorySize, SMEM_GEMM);
    cudaFuncSetAttribute(k_b2,   cudaFuncAttributeMaxDynamicSharedMemorySize, SMEM_GEMM);
    cudaFuncSetAttribute(k_c,    cudaFuncAttributeMaxDynamicSharedMemorySize, SMEM_GEMM);

    p_all <<<2304, 256>>>(hidden, comb, queries);
    k_gram<<<dim3(6, 8, 8), 128, SMEM_GEMM>>>();
    k_gred<<<512, 256>>>();
    k_b1  <<<dim3(8, 32), 128, SMEM_GEMM>>>();
    k_b2  <<<dim3(8, 8, 4), 128, SMEM_GEMM>>>();
    k_mred<<<512, 256>>>();
    k_c   <<<dim3(64, 8), 128, SMEM_GEMM>>>(out);
}

// round 15
// speedup vs baseline: 1.5588x; 1.2464x over previous
#include <cuda_runtime.h>
#include <cuda_fp16.h>
#include <cstdint>

typedef unsigned int u32;
typedef unsigned short u16;

// Scales: queries x1024, combiners x1024 => M scaled by 2^20; descale in k_c.
#define DESCALE (1.0f / 1048576.0f)

// ---------------------------------------------------------------------------
// Device-global scratch (no allocations allowed). All fp16 stored as ushort.
// ---------------------------------------------------------------------------
__device__ __align__(16) u16 g_XTh[8u*256*2048];                      // X^T hi per (b,q): [f=256][t=2048]
__device__ __align__(16) u16 g_Xnh[2u*2048*1024];                     // hidden hi: [b][t][e]
__device__ __align__(16) u16 g_CTh[16u*65536],   g_CTl[16u*65536];    // C^T (x1024) per (a,q): [g=256][f=256]
__device__ __align__(16) u16 g_qh [4u*262144];                        // queries (x1024) hi: [a][e=256][k=1024]
__device__ __align__(16) float g_Gp[8u*8*65536];                      // gram fp32 partials (z8); upper blocks only
__device__ __align__(16) u16 g_Gh[8u*65536];                          // G hi per (b,q): [256][256]
__device__ __align__(16) u16 g_TTh[8u*262144], g_TTl[8u*262144];      // T^T split: [ba][g=256][k=1024]
__device__ __align__(16) float g_Mp[4u*8*65536];                      // fold fp32 partials (z4)
__device__ __align__(16) u16 g_Mth[8u*65536];                         // M^T hi per (b,a): [g=256][e=256]

// ---------------------------------------------------------------------------
__device__ __forceinline__ void mma_f16(float* c, const u32* a, const u32* b) {
    asm("mma.sync.aligned.m16n8k16.row.col.f32.f16.f16.f32 "
        "{%0,%1,%2,%3}, {%4,%5,%6,%7}, {%8,%9}, {%0,%1,%2,%3};"
        : "+f"(c[0]), "+f"(c[1]), "+f"(c[2]), "+f"(c[3])
        : "r"(a[0]), "r"(a[1]), "r"(a[2]), "r"(a[3]), "r"(b[0]), "r"(b[1]));
}
__device__ __forceinline__ void ldsm_x4(u32* r, u32 saddr) {
    asm volatile("ldmatrix.sync.aligned.m8n8.x4.shared.b16 {%0,%1,%2,%3}, [%4];"
                 : "=r"(r[0]), "=r"(r[1]), "=r"(r[2]), "=r"(r[3]) : "r"(saddr));
}
__device__ __forceinline__ void cpa16(u32 dst, const void* src) {
    asm volatile("cp.async.cg.shared.global [%0], [%1], 16;" :: "r"(dst), "l"(src));
}
__device__ __forceinline__ void cpa_commit() {
    asm volatile("cp.async.commit_group;" ::: "memory");
}

// fp16 hi/lo split (round-to-nearest residual)
__device__ __forceinline__ void split2h(float v, u16& h, u16& l) {
    __half hh = __float2half_rn(v);
    __half ll = __float2half_rn(v - __half2float(hh));
    h = *reinterpret_cast<u16*>(&hh);
    l = *reinterpret_cast<u16*>(&ll);
}
__device__ __forceinline__ u16 hi_h(float v) {
    __half hh = __float2half_rn(v);
    return *reinterpret_cast<u16*>(&hh);
}

// SMEM tiles (row stride 40 u16 = 80B): A 128x32 (h[+l]), B 64x32 (h only).
constexpr int SK = 40;
constexpr int TSA = 128 * SK;                   // u16, A tile
constexpr int TSB = 64 * SK;                    // u16, B tile
constexpr int BUF = 2 * TSA + TSB;              // u16 per buffer = 12800 (Al slot may be unused)
constexpr int SMEM_GEMM = 2 * BUF * 2;          // bytes = 51200

// ---------------------------------------------------------------------------
// cp.async fill of one chunk (A 128x32 h[,l], B 64x32 h). 128 threads.
// ---------------------------------------------------------------------------
template <bool A_RESID>
__device__ __forceinline__ void issue_chunk(u16* buf,
    const u16* __restrict__ Ah, const u16* __restrict__ Al, size_t lda,
    const u16* __restrict__ Bh, size_t ldb, int k0)
{
    u16* sAh = buf;            u16* sAl = buf + TSA;
    u16* sBh = buf + 2 * TSA;
    #pragma unroll
    for (int u = threadIdx.x; u < 512; u += 128) {
        int row = u >> 2, c = u & 3;
        int so = row * SK + c * 8;
        size_t go = (size_t)row * lda + k0 + c * 8;
        cpa16((u32)__cvta_generic_to_shared(sAh + so), Ah + go);
        if (A_RESID)
            cpa16((u32)__cvta_generic_to_shared(sAl + so), Al + go);
    }
    #pragma unroll
    for (int u = threadIdx.x; u < 256; u += 128) {
        int row = u >> 2, c = u & 3;
        int so = row * SK + c * 8;
        size_t go = (size_t)row * ldb + k0 + c * 8;
        cpa16((u32)__cvta_generic_to_shared(sBh + so), Bh + go);
    }
    cpa_commit();
}

// ---------------------------------------------------------------------------
// Core: C[128,64](fp32) = sum_k A[128,k] * Bh[64,k]^T
//   A_RESID=true : A = Ah + Al (hh + lh terms, two accumulator sets)
//   A_RESID=false: A = Ah only (hh term)
// 128 threads = 4 warps (2m x 2n), warp tile 64x32.
// ---------------------------------------------------------------------------
template <bool SPLIT_OUT, bool A_RESID>
__device__ void gemm_ss(const u16* __restrict__ Ah, const u16* __restrict__ Al, size_t lda,
                        const u16* __restrict__ Bh, size_t ldb,
                        int kbeg, int kend,
                        float* __restrict__ C, u16* __restrict__ Ch, u16* __restrict__ Cl,
                        size_t ldc, float scale)
{
    extern __shared__ __align__(16) u16 dsmem[];
    u16* bufs[2] = { dsmem, dsmem + BUF };

    const int tid = threadIdx.x, w = tid >> 5, lane = tid & 31;
    const int wm = (w >> 1) * 64, wn = (w & 1) * 32;
    const int ty = lane >> 2, tk = lane & 3;

    float accA[4][4][4] = {};   // hh  [mt][nt(n8)][frag]
    float accB[4][4][4] = {};   // lh (unused when !A_RESID; compiler removes)

    const int nchunk = (kend - kbeg) >> 5;
    issue_chunk<A_RESID>(bufs[0], Ah, Al, lda, Bh, ldb, kbeg);

    for (int i = 0; i < nchunk; i++) {
        const bool has_next = (i + 1) < nchunk;
        if (has_next)
            issue_chunk<A_RESID>(bufs[(i + 1) & 1], Ah, Al, lda, Bh, ldb, kbeg + (i + 1) * 32);
        if (has_next) asm volatile("cp.async.wait_group 1;" ::: "memory");
        else          asm volatile("cp.async.wait_group 0;" ::: "memory");
        __syncthreads();

        u16* buf = bufs[i & 1];
        const u32 bAh = (u32)__cvta_generic_to_shared(buf);
        const u32 bAl = bAh + TSA * 2;
        const u32 bBh = bAh + 2 * TSA * 2;

        #pragma unroll
        for (int ks = 0; ks < 2; ks++) {
            const int kb = ks * 16;
            u32 bh[2][4];
            #pragma unroll
            for (int np = 0; np < 2; np++) {
                u32 off = ((wn + np * 16 + (lane & 7) + ((lane >> 4) & 1) * 8) * SK
                           + kb + ((lane >> 3) & 1) * 8) * 2;
                ldsm_x4(bh[np], bBh + off);
            }
            #pragma unroll
            for (int mt = 0; mt < 4; mt++) {
                u32 off = ((wm + mt * 16 + (lane & 15)) * SK + kb + (lane >> 4) * 8) * 2;
                u32 ah[4], al[4];
                ldsm_x4(ah, bAh + off);
                if (A_RESID) ldsm_x4(al, bAl + off);
                #pragma unroll
                for (int np = 0; np < 2; np++) {
                    mma_f16(accA[mt][2*np],   ah, bh[np]);
                    mma_f16(accA[mt][2*np+1], ah, bh[np] + 2);
                    if (A_RESID) {
                        mma_f16(accB[mt][2*np],   al, bh[np]);
                        mma_f16(accB[mt][2*np+1], al, bh[np] + 2);
                    }
                }
            }
        }
        __syncthreads();
    }

    #pragma unroll
    for (int mt = 0; mt < 4; mt++) {
        int m = wm + mt * 16 + ty;
        #pragma unroll
        for (int nt = 0; nt < 4; nt++) {
            int n = wn + nt * 8 + tk * 2;
            float c0, c1, c2, c3;
            if (A_RESID) {
                c0 = (accA[mt][nt][0] + accB[mt][nt][0]) * scale;
                c1 = (accA[mt][nt][1] + accB[mt][nt][1]) * scale;
                c2 = (accA[mt][nt][2] + accB[mt][nt][2]) * scale;
                c3 = (accA[mt][nt][3] + accB[mt][nt][3]) * scale;
            } else {
                c0 = accA[mt][nt][0] * scale;
                c1 = accA[mt][nt][1] * scale;
                c2 = accA[mt][nt][2] * scale;
                c3 = accA[mt][nt][3] * scale;
            }
            if (SPLIT_OUT) {
                u16 h0, l0, h1, l1, h2, l2, h3, l3;
                split2h(c0, h0, l0); split2h(c1, h1, l1);
                split2h(c2, h2, l2); split2h(c3, h3, l3);
                *reinterpret_cast<ushort2*>(&Ch[(size_t)m * ldc + n]) = make_ushort2(h0, h1);
                *reinterpret_cast<ushort2*>(&Cl[(size_t)m * ldc + n]) = make_ushort2(l0, l1);
                *reinterpret_cast<ushort2*>(&Ch[(size_t)(m + 8) * ldc + n]) = make_ushort2(h2, h3);
                *reinterpret_cast<ushort2*>(&Cl[(size_t)(m + 8) * ldc + n]) = make_ushort2(l2, l3);
            } else {
                *reinterpret_cast<float2*>(&C[(size_t)m * ldc + n]) = make_float2(c0, c1);
                *reinterpret_cast<float2*>(&C[(size_t)(m + 8) * ldc + n]) = make_float2(c2, c3);
            }
        }
    }
}

// ---------------------------------------------------------------------------
// Merged prep kernel (one launch):
// [0,1024) hidden hi + transpose-hi | [1024,1280) comb x1024 h/l | [1280,2304) queries x1024 hi
// ---------------------------------------------------------------------------
__global__ void __launch_bounds__(256) p_all(const float* __restrict__ hidden,
                                             const float* __restrict__ comb,
                                             const float* __restrict__ queries)
{
    __shared__ float tile[64][65];
    const int tid = threadIdx.x;
    const int bid = blockIdx.x;

    if (bid < 1024) {
        const int e0 = (bid & 15) * 64, t0 = ((bid >> 4) & 31) * 64, b = bid >> 9;
        const size_t base = (size_t)b * 2048 * 1024;
        for (int i = tid; i < 4096; i += 256) {
            int r = i >> 6, c = i & 63;
            float v = hidden[base + (size_t)(t0 + r) * 1024 + e0 + c];
            tile[r][c] = v;
            g_Xnh[base + (size_t)(t0 + r) * 1024 + e0 + c] = hi_h(v);
        }
        __syncthreads();
        const int pair = b * 4 + (e0 >> 8), f0 = e0 & 255;
        for (int i = tid; i < 4096; i += 256) {
            int fl = i >> 6, tl = i & 63;
            size_t o = (size_t)pair * 524288 + (size_t)(f0 + fl) * 2048 + t0 + tl;
            g_XTh[o] = hi_h(tile[tl][fl]);
        }
    } else if (bid < 1280) {
        const int j = bid - 1024;
        const int g0 = (j & 3) * 64, k0 = ((j >> 2) & 15) * 64, a = j >> 6;
        for (int i = tid; i < 4096; i += 256) {
            int r = i >> 6, c = i & 63;
            tile[r][c] = comb[(size_t)a * 262144 + (size_t)(k0 + r) * 256 + g0 + c] * 1024.0f;
        }
        __syncthreads();
        const int q = k0 >> 8, f0 = k0 & 255;
        for (int i = tid; i < 4096; i += 256) {
            int gl = i >> 6, fl = i & 63;
            u16 h, l; split2h(tile[fl][gl], h, l);
            size_t o = (size_t)(a * 4 + q) * 65536 + (size_t)(g0 + gl) * 256 + f0 + fl;
            g_CTh[o] = h; g_CTl[o] = l;
        }
    } else {
        const int i = (bid - 1280) * 256 + tid;            // 262144 float4
        float4 v = reinterpret_cast<const float4*>(queries)[i];
        ushort4 h = make_ushort4(hi_h(v.x * 1024.0f), hi_h(v.y * 1024.0f),
                                 hi_h(v.z * 1024.0f), hi_h(v.w * 1024.0f));
        reinterpret_cast<ushort4*>(g_qh)[i] = h;
    }
}

// ---------------------------------------------------------------------------
// Gram (SYMMETRIC upper, hh only): grid (6, 8 pairs, 8 z)
// ---------------------------------------------------------------------------
__global__ void __launch_bounds__(128) k_gram()
{
    const int pair = blockIdx.y, z = blockIdx.z;
    const int t = blockIdx.x;
    const int mi = (t >= 4) ? 1 : 0;
    const int ni = mi ? (t - 2) : t;
    const int m0 = mi * 128, n0 = ni * 64;
    const u16* base_h = g_XTh + (size_t)pair * 524288;
    float* C = g_Gp + (size_t)(z * 8 + pair) * 65536 + (size_t)m0 * 256 + n0;
    gemm_ss<false, false>(base_h + (size_t)m0 * 2048, nullptr, 2048,
                          base_h + (size_t)n0 * 2048, 2048,
                          z * 256, z * 256 + 256, C, nullptr, nullptr, 256, 1.0f);
}

// Reduce z-partials; mirror lower-left; store hi only.
__global__ void __launch_bounds__(256) k_gred()
{
    const int i = blockIdx.x * 256 + threadIdx.x;      // 131072 float4
    const int pair = i >> 14;
    const int off = i & 16383;
    const int r = off >> 6;
    const int c = (off & 63) * 4;
    float4 s;
    if (r >= 128 && c < 128) {
        float v0 = 0.f, v1 = 0.f, v2 = 0.f, v3 = 0.f;
        #pragma unroll
        for (int z = 0; z < 8; z++) {
            const float* P = g_Gp + (((size_t)z * 8 + pair) << 16);
            v0 += P[(size_t)(c + 0) * 256 + r];
            v1 += P[(size_t)(c + 1) * 256 + r];
            v2 += P[(size_t)(c + 2) * 256 + r];
            v3 += P[(size_t)(c + 3) * 256 + r];
        }
        s = make_float4(v0, v1, v2, v3);
    } else {
        const float4* P = reinterpret_cast<const float4*>(g_Gp);
        s = P[i];
        #pragma unroll
        for (int z = 1; z < 8; z++) {
            float4 t = P[i + (size_t)z * 131072];
            s.x += t.x; s.y += t.y; s.z += t.z; s.w += t.w;
        }
    }
    reinterpret_cast<ushort4*>(g_Gh)[i] =
        make_ushort4(hi_h(s.x), hi_h(s.y), hi_h(s.z), hi_h(s.w));
}

// B1: TT[ba][g, q*256+f] = sum_{f'} CT[a,q][g,f'] G[b,q][f,f'] — grid (8, 32)
__global__ void __launch_bounds__(128) k_b1()
{
    const int combo = blockIdx.y, q = combo & 3, ba = combo >> 2;
    const int a = ba & 3, b = ba >> 2;
    const int m0 = (blockIdx.x >> 2) * 128, n0 = (blockIdx.x & 3) * 64;
    const u16* Ah = g_CTh + (size_t)(a * 4 + q) * 65536 + (size_t)m0 * 256;
    const u16* Al = g_CTl + (size_t)(a * 4 + q) * 65536 + (size_t)m0 * 256;
    const u16* Bh = g_Gh + (size_t)(b * 4 + q) * 65536 + (size_t)n0 * 256;
    size_t off = (size_t)ba * 262144 + (size_t)m0 * 1024 + q * 256 + n0;
    gemm_ss<true, true>(Ah, Al, 256, Bh, 256, 0, 256,
                        nullptr, g_TTh + off, g_TTl + off, 1024, 1.0f);
}

// B2: M[g,e] = sum_k TT[ba][g,k] q[a][e,k] — grid (8, 8 ba, 4 z)
__global__ void __launch_bounds__(128) k_b2()
{
    const int ba = blockIdx.y, z = blockIdx.z, a = ba & 3;
    const int m0 = (blockIdx.x >> 2) * 128, n0 = (blockIdx.x & 3) * 64;
    const u16* Ah = g_TTh + (size_t)ba * 262144 + (size_t)m0 * 1024;
    const u16* Al = g_TTl + (size_t)ba * 262144 + (size_t)m0 * 1024;
    const u16* Bh = g_qh + (size_t)a * 262144 + (size_t)n0 * 1024;
    float* C = g_Mp + (size_t)(z * 8 + ba) * 65536 + (size_t)m0 * 256 + n0;
    gemm_ss<false, true>(Ah, Al, 1024, Bh, 1024, z * 256, z * 256 + 256,
                         C, nullptr, nullptr, 256, 1.0f);
}

// Reduce M partials; store hi only.
__global__ void __launch_bounds__(256) k_mred()
{
    const int i = blockIdx.x * 256 + threadIdx.x;      // 131072 float4
    const float4* P = reinterpret_cast<const float4*>(g_Mp);
    float4 s = P[i];
    #pragma unroll
    for (int z = 1; z < 4; z++) {
        float4 t = P[i + (size_t)z * 131072];
        s.x += t.x; s.y += t.y; s.z += t.z; s.w += t.w;
    }
    reinterpret_cast<ushort4*>(g_Mth)[i] =
        make_ushort4(hi_h(s.x), hi_h(s.y), hi_h(s.z), hi_h(s.w));
}

// C: out[b,t,a*256+g] = 2^-20 * sum_e Xn[b,t,a*256+e] Mt[ba][g,e] — grid (64, 8 ba)
// A = Xn hi only.
__global__ void __launch_bounds__(128) k_c(float* __restrict__ out)
{
    const int ba = blockIdx.y, b = ba >> 2, a = ba & 3;
    const int m0 = (blockIdx.x >> 2) * 128, n0 = (blockIdx.x & 3) * 64;
    const u16* Ah = g_Xnh + (size_t)b * 2097152 + (size_t)m0 * 1024 + a * 256;
    const u16* Bh = g_Mth + (size_t)ba * 65536 + (size_t)n0 * 256;
    float* C = out + (size_t)b * 2097152 + (size_t)m0 * 1024 + a * 256 + n0;
    gemm_ss<false, false>(Ah, nullptr, 1024, Bh, 256, 0, 256,
                          C, nullptr, nullptr, 1024, DESCALE);
}

// ---------------------------------------------------------------------------
extern "C" void kernel_launch(void* const* d_in, const int* in_sizes, int n_in,
                              void* d_out, int out_size)
{
    const float* hidden  = (const float*)d_in[0];   // [2, 2048, 1024]
    const float* queries = (const float*)d_in[1];   // [4, 256, 1024]
    const float* comb    = (const float*)d_in[2];   // [4, 1024, 256]
    float* out = (float*)d_out;                     // [2, 2048, 1024]

    cudaFuncSetAttribute(k_gram, cudaFuncAttributeMaxDynamicSharedMemorySize, SMEM_GEMM);
    cudaFuncSetAttribute(k_b1,   cudaFuncAttributeMaxDynamicSharedMemorySize, SMEM_GEMM);
    cudaFuncSetAttribute(k_b2,   cudaFuncAttributeMaxDynamicSharedMemorySize, SMEM_GEMM);
    cudaFuncSetAttribute(k_c,    cudaFuncAttributeMaxDynamicSharedMemorySize, SMEM_GEMM);

    p_all <<<2304, 256>>>(hidden, comb, queries);
    k_gram<<<dim3(6, 8, 8), 128, SMEM_GEMM>>>();
    k_gred<<<512, 256>>>();
    k_b1  <<<dim3(8, 32), 128, SMEM_GEMM>>>();
    k_b2  <<<dim3(8, 8, 4), 128, SMEM_GEMM>>>();
    k_mred<<<512, 256>>>();
    k_c   <<<dim3(64, 8), 128, SMEM_GEMM>>>(out);
}

// round 16
// speedup vs baseline: 1.8288x; 1.1732x over previous
#include <cuda_runtime.h>
#include <cuda_fp16.h>
#include <cstdint>

typedef unsigned int u32;
typedef unsigned short u16;

// Scales: queries x1024, combiners x1024 => M scaled by 2^20; descale in k_c.
#define DESCALE (1.0f / 1048576.0f)

// ---------------------------------------------------------------------------
// Device-global scratch (no allocations allowed). All fp16 stored as ushort.
// Single-term fp16 everywhere (error budget: ~4.9e-4 < 1e-3, calibrated).
// ---------------------------------------------------------------------------
__device__ __align__(16) u16 g_XTh[8u*256*2048];      // X^T hi per (b,q): [f=256][t=2048]
__device__ __align__(16) u16 g_Xnh[2u*2048*1024];     // hidden hi: [b][t][e]
__device__ __align__(16) u16 g_CTh[16u*65536];        // C^T (x1024) hi per (a,q): [g=256][f=256]
__device__ __align__(16) u16 g_qh [4u*262144];        // queries (x1024) hi: [a][e=256][k=1024]
__device__ __align__(16) float g_Gp[8u*8*65536];      // gram fp32 partials (z8); upper blocks only
__device__ __align__(16) u16 g_Gh[8u*65536];          // G hi per (b,q): [256][256]
__device__ __align__(16) u16 g_TTh[8u*262144];        // T^T hi: [ba][g=256][k=1024]
__device__ __align__(16) float g_Mp[4u*8*65536];      // fold fp32 partials (z4)
__device__ __align__(16) u16 g_Mth[8u*65536];         // M^T hi per (b,a): [g=256][e=256]

// ---------------------------------------------------------------------------
__device__ __forceinline__ void mma_f16(float* c, const u32* a, const u32* b) {
    asm("mma.sync.aligned.m16n8k16.row.col.f32.f16.f16.f32 "
        "{%0,%1,%2,%3}, {%4,%5,%6,%7}, {%8,%9}, {%0,%1,%2,%3};"
        : "+f"(c[0]), "+f"(c[1]), "+f"(c[2]), "+f"(c[3])
        : "r"(a[0]), "r"(a[1]), "r"(a[2]), "r"(a[3]), "r"(b[0]), "r"(b[1]));
}
__device__ __forceinline__ void ldsm_x4(u32* r, u32 saddr) {
    asm volatile("ldmatrix.sync.aligned.m8n8.x4.shared.b16 {%0,%1,%2,%3}, [%4];"
                 : "=r"(r[0]), "=r"(r[1]), "=r"(r[2]), "=r"(r[3]) : "r"(saddr));
}
__device__ __forceinline__ void cpa16(u32 dst, const void* src) {
    asm volatile("cp.async.cg.shared.global [%0], [%1], 16;" :: "r"(dst), "l"(src));
}
__device__ __forceinline__ void cpa_commit() {
    asm volatile("cp.async.commit_group;" ::: "memory");
}

__device__ __forceinline__ u16 hi_h(float v) {
    __half hh = __float2half_rn(v);
    return *reinterpret_cast<u16*>(&hh);
}

// SMEM tiles (row stride 40 u16 = 80B): A 128x32, B 64x32.
constexpr int SK = 40;
constexpr int TSA = 128 * SK;                   // u16, A tile
constexpr int TSB = 64 * SK;                    // u16, B tile
constexpr int BUF = TSA + TSB;                  // u16 per buffer = 7680
constexpr int SMEM_GEMM = 2 * BUF * 2;          // bytes = 30720

// ---------------------------------------------------------------------------
// cp.async fill of one chunk (A 128x32, B 64x32). 128 threads.
// ---------------------------------------------------------------------------
__device__ __forceinline__ void issue_chunk(u16* buf,
    const u16* __restrict__ A, size_t lda,
    const u16* __restrict__ B, size_t ldb, int k0)
{
    u16* sA = buf;
    u16* sB = buf + TSA;
    #pragma unroll
    for (int u = threadIdx.x; u < 512; u += 128) {
        int row = u >> 2, c = u & 3;
        int so = row * SK + c * 8;
        cpa16((u32)__cvta_generic_to_shared(sA + so), A + (size_t)row * lda + k0 + c * 8);
    }
    #pragma unroll
    for (int u = threadIdx.x; u < 256; u += 128) {
        int row = u >> 2, c = u & 3;
        int so = row * SK + c * 8;
        cpa16((u32)__cvta_generic_to_shared(sB + so), B + (size_t)row * ldb + k0 + c * 8);
    }
    cpa_commit();
}

// ---------------------------------------------------------------------------
// Core: C[128,64](fp32) = sum_k A[128,k] * B[64,k]^T  (single-term fp16)
// 128 threads = 4 warps (2m x 2n), warp tile 64x32. Double-buffered cp.async.
// OUT_F16: write fp16-hi u16 instead of fp32.
// ---------------------------------------------------------------------------
template <bool OUT_F16>
__device__ void gemm_ss(const u16* __restrict__ A, size_t lda,
                        const u16* __restrict__ B, size_t ldb,
                        int kbeg, int kend,
                        float* __restrict__ C, u16* __restrict__ Ch,
                        size_t ldc, float scale)
{
    extern __shared__ __align__(16) u16 dsmem[];
    u16* bufs[2] = { dsmem, dsmem + BUF };

    const int tid = threadIdx.x, w = tid >> 5, lane = tid & 31;
    const int wm = (w >> 1) * 64, wn = (w & 1) * 32;
    const int ty = lane >> 2, tk = lane & 3;

    float acc[4][4][4] = {};   // [mt][nt(n8)][frag]

    const int nchunk = (kend - kbeg) >> 5;
    issue_chunk(bufs[0], A, lda, B, ldb, kbeg);

    for (int i = 0; i < nchunk; i++) {
        const bool has_next = (i + 1) < nchunk;
        if (has_next)
            issue_chunk(bufs[(i + 1) & 1], A, lda, B, ldb, kbeg + (i + 1) * 32);
        if (has_next) asm volatile("cp.async.wait_group 1;" ::: "memory");
        else          asm volatile("cp.async.wait_group 0;" ::: "memory");
        __syncthreads();

        u16* buf = bufs[i & 1];
        const u32 bA = (u32)__cvta_generic_to_shared(buf);
        const u32 bB = bA + TSA * 2;

        #pragma unroll
        for (int ks = 0; ks < 2; ks++) {
            const int kb = ks * 16;
            u32 bh[2][4];
            #pragma unroll
            for (int np = 0; np < 2; np++) {
                u32 off = ((wn + np * 16 + (lane & 7) + ((lane >> 4) & 1) * 8) * SK
                           + kb + ((lane >> 3) & 1) * 8) * 2;
                ldsm_x4(bh[np], bB + off);
            }
            #pragma unroll
            for (int mt = 0; mt < 4; mt++) {
                u32 off = ((wm + mt * 16 + (lane & 15)) * SK + kb + (lane >> 4) * 8) * 2;
                u32 ah[4];
                ldsm_x4(ah, bA + off);
                #pragma unroll
                for (int np = 0; np < 2; np++) {
                    mma_f16(acc[mt][2*np],   ah, bh[np]);
                    mma_f16(acc[mt][2*np+1], ah, bh[np] + 2);
                }
            }
        }
        __syncthreads();
    }

    #pragma unroll
    for (int mt = 0; mt < 4; mt++) {
        int m = wm + mt * 16 + ty;
        #pragma unroll
        for (int nt = 0; nt < 4; nt++) {
            int n = wn + nt * 8 + tk * 2;
            float c0 = acc[mt][nt][0] * scale;
            float c1 = acc[mt][nt][1] * scale;
            float c2 = acc[mt][nt][2] * scale;
            float c3 = acc[mt][nt][3] * scale;
            if (OUT_F16) {
                *reinterpret_cast<ushort2*>(&Ch[(size_t)m * ldc + n]) =
                    make_ushort2(hi_h(c0), hi_h(c1));
                *reinterpret_cast<ushort2*>(&Ch[(size_t)(m + 8) * ldc + n]) =
                    make_ushort2(hi_h(c2), hi_h(c3));
            } else {
                *reinterpret_cast<float2*>(&C[(size_t)m * ldc + n]) = make_float2(c0, c1);
                *reinterpret_cast<float2*>(&C[(size_t)(m + 8) * ldc + n]) = make_float2(c2, c3);
            }
        }
    }
}

// ---------------------------------------------------------------------------
// Merged prep kernel (one launch):
// [0,1024) hidden hi + transpose-hi | [1024,1280) comb x1024 hi | [1280,2304) queries x1024 hi
// ---------------------------------------------------------------------------
__global__ void __launch_bounds__(256) p_all(const float* __restrict__ hidden,
                                             const float* __restrict__ comb,
                                             const float* __restrict__ queries)
{
    __shared__ float tile[64][65];
    const int tid = threadIdx.x;
    const int bid = blockIdx.x;

    if (bid < 1024) {
        const int e0 = (bid & 15) * 64, t0 = ((bid >> 4) & 31) * 64, b = bid >> 9;
        const size_t base = (size_t)b * 2048 * 1024;
        for (int i = tid; i < 4096; i += 256) {
            int r = i >> 6, c = i & 63;
            float v = hidden[base + (size_t)(t0 + r) * 1024 + e0 + c];
            tile[r][c] = v;
            g_Xnh[base + (size_t)(t0 + r) * 1024 + e0 + c] = hi_h(v);
        }
        __syncthreads();
        const int pair = b * 4 + (e0 >> 8), f0 = e0 & 255;
        for (int i = tid; i < 4096; i += 256) {
            int fl = i >> 6, tl = i & 63;
            size_t o = (size_t)pair * 524288 + (size_t)(f0 + fl) * 2048 + t0 + tl;
            g_XTh[o] = hi_h(tile[tl][fl]);
        }
    } else if (bid < 1280) {
        const int j = bid - 1024;
        const int g0 = (j & 3) * 64, k0 = ((j >> 2) & 15) * 64, a = j >> 6;
        for (int i = tid; i < 4096; i += 256) {
            int r = i >> 6, c = i & 63;
            tile[r][c] = comb[(size_t)a * 262144 + (size_t)(k0 + r) * 256 + g0 + c] * 1024.0f;
        }
        __syncthreads();
        const int q = k0 >> 8, f0 = k0 & 255;
        for (int i = tid; i < 4096; i += 256) {
            int gl = i >> 6, fl = i & 63;
            size_t o = (size_t)(a * 4 + q) * 65536 + (size_t)(g0 + gl) * 256 + f0 + fl;
            g_CTh[o] = hi_h(tile[fl][gl]);
        }
    } else {
        const int i = (bid - 1280) * 256 + tid;            // 262144 float4
        float4 v = reinterpret_cast<const float4*>(queries)[i];
        reinterpret_cast<ushort4*>(g_qh)[i] =
            make_ushort4(hi_h(v.x * 1024.0f), hi_h(v.y * 1024.0f),
                         hi_h(v.z * 1024.0f), hi_h(v.w * 1024.0f));
    }
}

// ---------------------------------------------------------------------------
// Gram (SYMMETRIC upper): grid (6, 8 pairs, 8 z); t<4:(0,t), t=4:(1,2), t=5:(1,3)
// ---------------------------------------------------------------------------
__global__ void __launch_bounds__(128) k_gram()
{
    const int pair = blockIdx.y, z = blockIdx.z;
    const int t = blockIdx.x;
    const int mi = (t >= 4) ? 1 : 0;
    const int ni = mi ? (t - 2) : t;
    const int m0 = mi * 128, n0 = ni * 64;
    const u16* base_h = g_XTh + (size_t)pair * 524288;
    float* C = g_Gp + (size_t)(z * 8 + pair) * 65536 + (size_t)m0 * 256 + n0;
    gemm_ss<false>(base_h + (size_t)m0 * 2048, 2048,
                   base_h + (size_t)n0 * 2048, 2048,
                   z * 256, z * 256 + 256, C, nullptr, 256, 1.0f);
}

// Reduce z-partials; mirror lower-left; store hi.
__global__ void __launch_bounds__(256) k_gred()
{
    const int i = blockIdx.x * 256 + threadIdx.x;      // 131072 float4
    const int pair = i >> 14;
    const int off = i & 16383;
    const int r = off >> 6;
    const int c = (off & 63) * 4;
    float4 s;
    if (r >= 128 && c < 128) {
        float v0 = 0.f, v1 = 0.f, v2 = 0.f, v3 = 0.f;
        #pragma unroll
        for (int z = 0; z < 8; z++) {
            const float* P = g_Gp + (((size_t)z * 8 + pair) << 16);
            v0 += P[(size_t)(c + 0) * 256 + r];
            v1 += P[(size_t)(c + 1) * 256 + r];
            v2 += P[(size_t)(c + 2) * 256 + r];
            v3 += P[(size_t)(c + 3) * 256 + r];
        }
        s = make_float4(v0, v1, v2, v3);
    } else {
        const float4* P = reinterpret_cast<const float4*>(g_Gp);
        s = P[i];
        #pragma unroll
        for (int z = 1; z < 8; z++) {
            float4 t = P[i + (size_t)z * 131072];
            s.x += t.x; s.y += t.y; s.z += t.z; s.w += t.w;
        }
    }
    reinterpret_cast<ushort4*>(g_Gh)[i] =
        make_ushort4(hi_h(s.x), hi_h(s.y), hi_h(s.z), hi_h(s.w));
}

// B1: TT[ba][g, q*256+f] = sum_{f'} CT[a,q][g,f'] G[b,q][f,f'] — grid (8, 32)
__global__ void __launch_bounds__(128) k_b1()
{
    const int combo = blockIdx.y, q = combo & 3, ba = combo >> 2;
    const int a = ba & 3, b = ba >> 2;
    const int m0 = (blockIdx.x >> 2) * 128, n0 = (blockIdx.x & 3) * 64;
    const u16* A = g_CTh + (size_t)(a * 4 + q) * 65536 + (size_t)m0 * 256;
    const u16* B = g_Gh + (size_t)(b * 4 + q) * 65536 + (size_t)n0 * 256;
    size_t off = (size_t)ba * 262144 + (size_t)m0 * 1024 + q * 256 + n0;
    gemm_ss<true>(A, 256, B, 256, 0, 256, nullptr, g_TTh + off, 1024, 1.0f);
}

// B2: M[g,e] = sum_k TT[ba][g,k] q[a][e,k] — grid (8, 8 ba, 4 z)
__global__ void __launch_bounds__(128) k_b2()
{
    const int ba = blockIdx.y, z = blockIdx.z, a = ba & 3;
    const int m0 = (blockIdx.x >> 2) * 128, n0 = (blockIdx.x & 3) * 64;
    const u16* A = g_TTh + (size_t)ba * 262144 + (size_t)m0 * 1024;
    const u16* B = g_qh + (size_t)a * 262144 + (size_t)n0 * 1024;
    float* C = g_Mp + (size_t)(z * 8 + ba) * 65536 + (size_t)m0 * 256 + n0;
    gemm_ss<false>(A, 1024, B, 1024, z * 256, z * 256 + 256, C, nullptr, 256, 1.0f);
}

// Reduce M partials; store hi.
__global__ void __launch_bounds__(256) k_mred()
{
    const int i = blockIdx.x * 256 + threadIdx.x;      // 131072 float4
    const float4* P = reinterpret_cast<const float4*>(g_Mp);
    float4 s = P[i];
    #pragma unroll
    for (int z = 1; z < 4; z++) {
        float4 t = P[i + (size_t)z * 131072];
        s.x += t.x; s.y += t.y; s.z += t.z; s.w += t.w;
    }
    reinterpret_cast<ushort4*>(g_Mth)[i] =
        make_ushort4(hi_h(s.x), hi_h(s.y), hi_h(s.z), hi_h(s.w));
}

// C: out[b,t,a*256+g] = 2^-20 * sum_e Xn[b,t,a*256+e] Mt[ba][g,e] — grid (64, 8 ba)
__global__ void __launch_bounds__(128) k_c(float* __restrict__ out)
{
    const int ba = blockIdx.y, b = ba >> 2, a = ba & 3;
    const int m0 = (blockIdx.x >> 2) * 128, n0 = (blockIdx.x & 3) * 64;
    const u16* A = g_Xnh + (size_t)b * 2097152 + (size_t)m0 * 1024 + a * 256;
    const u16* B = g_Mth + (size_t)ba * 65536 + (size_t)n0 * 256;
    float* C = out + (size_t)b * 2097152 + (size_t)m0 * 1024 + a * 256 + n0;
    gemm_ss<false>(A, 1024, B, 256, 0, 256, C, nullptr, 1024, DESCALE);
}

// ---------------------------------------------------------------------------
extern "C" void kernel_launch(void* const* d_in, const int* in_sizes, int n_in,
                              void* d_out, int out_size)
{
    const float* hidden  = (const float*)d_in[0];   // [2, 2048, 1024]
    const float* queries = (const float*)d_in[1];   // [4, 256, 1024]
    const float* comb    = (const float*)d_in[2];   // [4, 1024, 256]
    float* out = (float*)d_out;                     // [2, 2048, 1024]

    cudaFuncSetAttribute(k_gram, cudaFuncAttributeMaxDynamicSharedMemorySize, SMEM_GEMM);
    cudaFuncSetAttribute(k_b1,   cudaFuncAttributeMaxDynamicSharedMemorySize, SMEM_GEMM);
    cudaFuncSetAttribute(k_b2,   cudaFuncAttributeMaxDynamicSharedMemorySize, SMEM_GEMM);
    cudaFuncSetAttribute(k_c,    cudaFuncAttributeMaxDynamicSharedMemorySize, SMEM_GEMM);

    p_all <<<2304, 256>>>(hidden, comb, queries);
    k_gram<<<dim3(6, 8, 8), 128, SMEM_GEMM>>>();
    k_gred<<<512, 256>>>();
    k_b1  <<<dim3(8, 32), 128, SMEM_GEMM>>>();
    k_b2  <<<dim3(8, 8, 4), 128, SMEM_GEMM>>>();
    k_mred<<<512, 256>>>();
    k_c   <<<dim3(64, 8), 128, SMEM_GEMM>>>(out);
}

// round 17
// speedup vs baseline: 1.8760x; 1.0258x over previous
#include <cuda_runtime.h>
#include <cuda_fp16.h>
#include <cstdint>

typedef unsigned int u32;
typedef unsigned short u16;

// Scales: queries x1024, combiners x1024 => M scaled by 2^20; descale in k_c.
#define DESCALE (1.0f / 1048576.0f)

// ---------------------------------------------------------------------------
// Device-global scratch (no allocations allowed). All fp16 stored as ushort.
// Single-term fp16 everywhere (error budget calibrated: ~5.2e-4 < 1e-3).
// ---------------------------------------------------------------------------
__device__ __align__(16) u16 g_XTh[8u*256*2048];      // X^T hi per (b,q): [f=256][t=2048]
__device__ __align__(16) u16 g_Xnh[2u*2048*1024];     // hidden hi: [b][t][e]
__device__ __align__(16) u16 g_CTh[16u*65536];        // C^T (x1024) hi per (a,q): [g=256][f=256]
__device__ __align__(16) u16 g_qh [4u*262144];        // queries (x1024) hi: [a][e=256][k=1024]
__device__ __align__(16) float g_Gp[8u*8*65536];      // gram fp32 partials (z8); upper blocks only
__device__ __align__(16) u16 g_Gh[8u*65536];          // G hi per (b,q): [256][256]
__device__ __align__(16) u16 g_TTh[8u*262144];        // T^T hi: [ba][g=256][k=1024]
__device__ __align__(16) float g_Mp[4u*8*65536];      // fold fp32 partials (z4)
__device__ __align__(16) u16 g_Mth[8u*65536];         // M^T hi per (b,a): [g=256][e=256]

// ---------------------------------------------------------------------------
__device__ __forceinline__ void mma_f16(float* c, const u32* a, const u32* b) {
    asm("mma.sync.aligned.m16n8k16.row.col.f32.f16.f16.f32 "
        "{%0,%1,%2,%3}, {%4,%5,%6,%7}, {%8,%9}, {%0,%1,%2,%3};"
        : "+f"(c[0]), "+f"(c[1]), "+f"(c[2]), "+f"(c[3])
        : "r"(a[0]), "r"(a[1]), "r"(a[2]), "r"(a[3]), "r"(b[0]), "r"(b[1]));
}
__device__ __forceinline__ void ldsm_x4(u32* r, u32 saddr) {
    asm volatile("ldmatrix.sync.aligned.m8n8.x4.shared.b16 {%0,%1,%2,%3}, [%4];"
                 : "=r"(r[0]), "=r"(r[1]), "=r"(r[2]), "=r"(r[3]) : "r"(saddr));
}
__device__ __forceinline__ void cpa16(u32 dst, const void* src) {
    asm volatile("cp.async.cg.shared.global [%0], [%1], 16;" :: "r"(dst), "l"(src));
}
__device__ __forceinline__ void cpa_commit() {
    asm volatile("cp.async.commit_group;" ::: "memory");
}

__device__ __forceinline__ u16 hi_h(float v) {
    __half hh = __float2half_rn(v);
    return *reinterpret_cast<u16*>(&hh);
}

// SMEM tiles (row stride 40 u16 = 80B): A 128x32, B 64x32. 3-stage ring.
constexpr int SK = 40;
constexpr int TSA = 128 * SK;                   // u16, A tile
constexpr int TSB = 64 * SK;                    // u16, B tile
constexpr int BUF = TSA + TSB;                  // u16 per stage = 7680
constexpr int NSTAGE = 3;
constexpr int SMEM_GEMM = NSTAGE * BUF * 2;     // bytes = 46080

// ---------------------------------------------------------------------------
// cp.async fill of one chunk (A 128x32, B 64x32). 128 threads.
// ---------------------------------------------------------------------------
__device__ __forceinline__ void issue_chunk(u16* buf,
    const u16* __restrict__ A, size_t lda,
    const u16* __restrict__ B, size_t ldb, int k0)
{
    u16* sA = buf;
    u16* sB = buf + TSA;
    #pragma unroll
    for (int u = threadIdx.x; u < 512; u += 128) {
        int row = u >> 2, c = u & 3;
        int so = row * SK + c * 8;
        cpa16((u32)__cvta_generic_to_shared(sA + so), A + (size_t)row * lda + k0 + c * 8);
    }
    #pragma unroll
    for (int u = threadIdx.x; u < 256; u += 128) {
        int row = u >> 2, c = u & 3;
        int so = row * SK + c * 8;
        cpa16((u32)__cvta_generic_to_shared(sB + so), B + (size_t)row * ldb + k0 + c * 8);
    }
    cpa_commit();
}

// ---------------------------------------------------------------------------
// Core: C[128,64](fp32) = sum_k A[128,k] * B[64,k]^T  (single-term fp16)
// 128 threads = 4 warps (2m x 2n), warp tile 64x32.
// 3-stage cp.async ring: chunk i awaited TWO iterations after issue.
// ---------------------------------------------------------------------------
template <bool OUT_F16>
__device__ void gemm_ss(const u16* __restrict__ A, size_t lda,
                        const u16* __restrict__ B, size_t ldb,
                        int kbeg, int kend,
                        float* __restrict__ C, u16* __restrict__ Ch,
                        size_t ldc, float scale)
{
    extern __shared__ __align__(16) u16 dsmem[];
    u16* bufs[NSTAGE] = { dsmem, dsmem + BUF, dsmem + 2 * BUF };

    const int tid = threadIdx.x, w = tid >> 5, lane = tid & 31;
    const int wm = (w >> 1) * 64, wn = (w & 1) * 32;
    const int ty = lane >> 2, tk = lane & 3;

    float acc[4][4][4] = {};   // [mt][nt(n8)][frag]

    const int nchunk = (kend - kbeg) >> 5;
    issue_chunk(bufs[0], A, lda, B, ldb, kbeg);
    if (nchunk > 1) issue_chunk(bufs[1], A, lda, B, ldb, kbeg + 32);

    int sidx = 0;  // buffer index of chunk i
    for (int i = 0; i < nchunk; i++) {
        // in flight now: chunks i..min(i+1, nchunk-1). Wait until chunk i done.
        if (i + 1 < nchunk) asm volatile("cp.async.wait_group 1;" ::: "memory");
        else                asm volatile("cp.async.wait_group 0;" ::: "memory");
        __syncthreads();   // also guarantees everyone finished compute on buf[(i+2)%3]

        if (i + 2 < nchunk) {
            int nidx = sidx + 2; if (nidx >= NSTAGE) nidx -= NSTAGE;
            issue_chunk(bufs[nidx], A, lda, B, ldb, kbeg + (i + 2) * 32);
        }

        const u32 bA = (u32)__cvta_generic_to_shared(bufs[sidx]);
        const u32 bB = bA + TSA * 2;

        #pragma unroll
        for (int ks = 0; ks < 2; ks++) {
            const int kb = ks * 16;
            u32 bh[2][4];
            #pragma unroll
            for (int np = 0; np < 2; np++) {
                u32 off = ((wn + np * 16 + (lane & 7) + ((lane >> 4) & 1) * 8) * SK
                           + kb + ((lane >> 3) & 1) * 8) * 2;
                ldsm_x4(bh[np], bB + off);
            }
            #pragma unroll
            for (int mt = 0; mt < 4; mt++) {
                u32 off = ((wm + mt * 16 + (lane & 15)) * SK + kb + (lane >> 4) * 8) * 2;
                u32 ah[4];
                ldsm_x4(ah, bA + off);
                #pragma unroll
                for (int np = 0; np < 2; np++) {
                    mma_f16(acc[mt][2*np],   ah, bh[np]);
                    mma_f16(acc[mt][2*np+1], ah, bh[np] + 2);
                }
            }
        }
        if (++sidx >= NSTAGE) sidx = 0;
    }

    #pragma unroll
    for (int mt = 0; mt < 4; mt++) {
        int m = wm + mt * 16 + ty;
        #pragma unroll
        for (int nt = 0; nt < 4; nt++) {
            int n = wn + nt * 8 + tk * 2;
            float c0 = acc[mt][nt][0] * scale;
            float c1 = acc[mt][nt][1] * scale;
            float c2 = acc[mt][nt][2] * scale;
            float c3 = acc[mt][nt][3] * scale;
            if (OUT_F16) {
                *reinterpret_cast<ushort2*>(&Ch[(size_t)m * ldc + n]) =
                    make_ushort2(hi_h(c0), hi_h(c1));
                *reinterpret_cast<ushort2*>(&Ch[(size_t)(m + 8) * ldc + n]) =
                    make_ushort2(hi_h(c2), hi_h(c3));
            } else {
                *reinterpret_cast<float2*>(&C[(size_t)m * ldc + n]) = make_float2(c0, c1);
                *reinterpret_cast<float2*>(&C[(size_t)(m + 8) * ldc + n]) = make_float2(c2, c3);
            }
        }
    }
}

// ---------------------------------------------------------------------------
// Merged prep kernel (one launch):
// [0,1024) hidden hi + transpose-hi | [1024,1280) comb x1024 hi | [1280,2304) queries x1024 hi
// ---------------------------------------------------------------------------
__global__ void __launch_bounds__(256) p_all(const float* __restrict__ hidden,
                                             const float* __restrict__ comb,
                                             const float* __restrict__ queries)
{
    __shared__ float tile[64][65];
    const int tid = threadIdx.x;
    const int bid = blockIdx.x;

    if (bid < 1024) {
        const int e0 = (bid & 15) * 64, t0 = ((bid >> 4) & 31) * 64, b = bid >> 9;
        const size_t base = (size_t)b * 2048 * 1024;
        for (int i = tid; i < 4096; i += 256) {
            int r = i >> 6, c = i & 63;
            float v = hidden[base + (size_t)(t0 + r) * 1024 + e0 + c];
            tile[r][c] = v;
            g_Xnh[base + (size_t)(t0 + r) * 1024 + e0 + c] = hi_h(v);
        }
        __syncthreads();
        const int pair = b * 4 + (e0 >> 8), f0 = e0 & 255;
        for (int i = tid; i < 4096; i += 256) {
            int fl = i >> 6, tl = i & 63;
            size_t o = (size_t)pair * 524288 + (size_t)(f0 + fl) * 2048 + t0 + tl;
            g_XTh[o] = hi_h(tile[tl][fl]);
        }
    } else if (bid < 1280) {
        const int j = bid - 1024;
        const int g0 = (j & 3) * 64, k0 = ((j >> 2) & 15) * 64, a = j >> 6;
        for (int i = tid; i < 4096; i += 256) {
            int r = i >> 6, c = i & 63;
            tile[r][c] = comb[(size_t)a * 262144 + (size_t)(k0 + r) * 256 + g0 + c] * 1024.0f;
        }
        __syncthreads();
        const int q = k0 >> 8, f0 = k0 & 255;
        for (int i = tid; i < 4096; i += 256) {
            int gl = i >> 6, fl = i & 63;
            size_t o = (size_t)(a * 4 + q) * 65536 + (size_t)(g0 + gl) * 256 + f0 + fl;
            g_CTh[o] = hi_h(tile[fl][gl]);
        }
    } else {
        const int i = (bid - 1280) * 256 + tid;            // 262144 float4
        float4 v = reinterpret_cast<const float4*>(queries)[i];
        reinterpret_cast<ushort4*>(g_qh)[i] =
            make_ushort4(hi_h(v.x * 1024.0f), hi_h(v.y * 1024.0f),
                         hi_h(v.z * 1024.0f), hi_h(v.w * 1024.0f));
    }
}

// ---------------------------------------------------------------------------
// Gram (SYMMETRIC upper): grid (6, 8 pairs, 8 z); t<4:(0,t), t=4:(1,2), t=5:(1,3)
// ---------------------------------------------------------------------------
__global__ void __launch_bounds__(128) k_gram()
{
    const int pair = blockIdx.y, z = blockIdx.z;
    const int t = blockIdx.x;
    const int mi = (t >= 4) ? 1 : 0;
    const int ni = mi ? (t - 2) : t;
    const int m0 = mi * 128, n0 = ni * 64;
    const u16* base_h = g_XTh + (size_t)pair * 524288;
    float* C = g_Gp + (size_t)(z * 8 + pair) * 65536 + (size_t)m0 * 256 + n0;
    gemm_ss<false>(base_h + (size_t)m0 * 2048, 2048,
                   base_h + (size_t)n0 * 2048, 2048,
                   z * 256, z * 256 + 256, C, nullptr, 256, 1.0f);
}

// Reduce z-partials; mirror lower-left; store hi.
__global__ void __launch_bounds__(256) k_gred()
{
    const int i = blockIdx.x * 256 + threadIdx.x;      // 131072 float4
    const int pair = i >> 14;
    const int off = i & 16383;
    const int r = off >> 6;
    const int c = (off & 63) * 4;
    float4 s;
    if (r >= 128 && c < 128) {
        float v0 = 0.f, v1 = 0.f, v2 = 0.f, v3 = 0.f;
        #pragma unroll
        for (int z = 0; z < 8; z++) {
            const float* P = g_Gp + (((size_t)z * 8 + pair) << 16);
            v0 += P[(size_t)(c + 0) * 256 + r];
            v1 += P[(size_t)(c + 1) * 256 + r];
            v2 += P[(size_t)(c + 2) * 256 + r];
            v3 += P[(size_t)(c + 3) * 256 + r];
        }
        s = make_float4(v0, v1, v2, v3);
    } else {
        const float4* P = reinterpret_cast<const float4*>(g_Gp);
        s = P[i];
        #pragma unroll
        for (int z = 1; z < 8; z++) {
            float4 t = P[i + (size_t)z * 131072];
            s.x += t.x; s.y += t.y; s.z += t.z; s.w += t.w;
        }
    }
    reinterpret_cast<ushort4*>(g_Gh)[i] =
        make_ushort4(hi_h(s.x), hi_h(s.y), hi_h(s.z), hi_h(s.w));
}

// B1: TT[ba][g, q*256+f] = sum_{f'} CT[a,q][g,f'] G[b,q][f,f'] — grid (8, 32)
__global__ void __launch_bounds__(128) k_b1()
{
    const int combo = blockIdx.y, q = combo & 3, ba = combo >> 2;
    const int a = ba & 3, b = ba >> 2;
    const int m0 = (blockIdx.x >> 2) * 128, n0 = (blockIdx.x & 3) * 64;
    const u16* A = g_CTh + (size_t)(a * 4 + q) * 65536 + (size_t)m0 * 256;
    const u16* B = g_Gh + (size_t)(b * 4 + q) * 65536 + (size_t)n0 * 256;
    size_t off = (size_t)ba * 262144 + (size_t)m0 * 1024 + q * 256 + n0;
    gemm_ss<true>(A, 256, B, 256, 0, 256, nullptr, g_TTh + off, 1024, 1.0f);
}

// B2: M[g,e] = sum_k TT[ba][g,k] q[a][e,k] — grid (8, 8 ba, 4 z)
__global__ void __launch_bounds__(128) k_b2()
{
    const int ba = blockIdx.y, z = blockIdx.z, a = ba & 3;
    const int m0 = (blockIdx.x >> 2) * 128, n0 = (blockIdx.x & 3) * 64;
    const u16* A = g_TTh + (size_t)ba * 262144 + (size_t)m0 * 1024;
    const u16* B = g_qh + (size_t)a * 262144 + (size_t)n0 * 1024;
    float* C = g_Mp + (size_t)(z * 8 + ba) * 65536 + (size_t)m0 * 256 + n0;
    gemm_ss<false>(A, 1024, B, 1024, z * 256, z * 256 + 256, C, nullptr, 256, 1.0f);
}

// Reduce M partials; store hi.
__global__ void __launch_bounds__(256) k_mred()
{
    const int i = blockIdx.x * 256 + threadIdx.x;      // 131072 float4
    const float4* P = reinterpret_cast<const float4*>(g_Mp);
    float4 s = P[i];
    #pragma unroll
    for (int z = 1; z < 4; z++) {
        float4 t = P[i + (size_t)z * 131072];
        s.x += t.x; s.y += t.y; s.z += t.z; s.w += t.w;
    }
    reinterpret_cast<ushort4*>(g_Mth)[i] =
        make_ushort4(hi_h(s.x), hi_h(s.y), hi_h(s.z), hi_h(s.w));
}

// C: out[b,t,a*256+g] = 2^-20 * sum_e Xn[b,t,a*256+e] Mt[ba][g,e] — grid (64, 8 ba)
__global__ void __launch_bounds__(128) k_c(float* __restrict__ out)
{
    const int ba = blockIdx.y, b = ba >> 2, a = ba & 3;
    const int m0 = (blockIdx.x >> 2) * 128, n0 = (blockIdx.x & 3) * 64;
    const u16* A = g_Xnh + (size_t)b * 2097152 + (size_t)m0 * 1024 + a * 256;
    const u16* B = g_Mth + (size_t)ba * 65536 + (size_t)n0 * 256;
    float* C = out + (size_t)b * 2097152 + (size_t)m0 * 1024 + a * 256 + n0;
    gemm_ss<false>(A, 1024, B, 256, 0, 256, C, nullptr, 1024, DESCALE);
}

// ---------------------------------------------------------------------------
extern "C" void kernel_launch(void* const* d_in, const int* in_sizes, int n_in,
                              void* d_out, int out_size)
{
    const float* hidden  = (const float*)d_in[0];   // [2, 2048, 1024]
    const float* queries = (const float*)d_in[1];   // [4, 256, 1024]
    const float* comb    = (const float*)d_in[2];   // [4, 1024, 256]
    float* out = (float*)d_out;                     // [2, 2048, 1024]

    cudaFuncSetAttribute(k_gram, cudaFuncAttributeMaxDynamicSharedMemorySize, SMEM_GEMM);
    cudaFuncSetAttribute(k_b1,   cudaFuncAttributeMaxDynamicSharedMemorySize, SMEM_GEMM);
    cudaFuncSetAttribute(k_b2,   cudaFuncAttributeMaxDynamicSharedMemorySize, SMEM_GEMM);
    cudaFuncSetAttribute(k_c,    cudaFuncAttributeMaxDynamicSharedMemorySize, SMEM_GEMM);

    p_all <<<2304, 256>>>(hidden, comb, queries);
    k_gram<<<dim3(6, 8, 8), 128, SMEM_GEMM>>>();
    k_gred<<<512, 256>>>();
    k_b1  <<<dim3(8, 32), 128, SMEM_GEMM>>>();
    k_b2  <<<dim3(8, 8, 4), 128, SMEM_GEMM>>>();
    k_mred<<<512, 256>>>();
    k_c   <<<dim3(64, 8), 128, SMEM_GEMM>>>(out);
}